// round 5
// baseline (speedup 1.0000x reference)
#include <cuda_runtime.h>
#include <cstdint>

#define HIDDEN 128
#define NCOEF  8
#define NPROTO 256
#define NMAX   131072
#define RPB    64
#define TILE_M 128
#define NCHUNK 36            // 1152 / 32
#define KDIM   1152
#define TAU    4e-4f

// ---------------- device scratch ----------------
__device__ float g_Wh1[NCHUNK * 4096];
__device__ float g_Wl1[NCHUNK * 4096];
__device__ float g_Wh2[NCHUNK * 4096];
__device__ float g_Wl2[NCHUNK * 4096];
__device__ float g_Wf1[KDIM * HIDDEN];     // fp32 combined, [k][o]
__device__ float g_Wf2[KDIM * HIDDEN];
__device__ float g_h[(size_t)NMAX * HIDDEN];
__device__ float g_pn[NPROTO * HIDDEN];    // normalized protos [p][i]
__device__ float g_pnT[HIDDEN * NPROTO];   // transposed [i][p]
__device__ float g_gp[2];                  // g0, invh
__device__ int   g_cnt;
__device__ int   g_list[NMAX];

// ---------------- helpers ----------------
__device__ __forceinline__ void tf32_split(float v, uint32_t& hi, uint32_t& lo) {
    asm("cvt.rna.tf32.f32 %0, %1;" : "=r"(hi) : "f"(v));
    float r = v - __uint_as_float(hi);
    asm("cvt.rna.tf32.f32 %0, %1;" : "=r"(lo) : "f"(r));
}
__device__ __forceinline__ void mma8(float* c, const uint32_t* a, const uint32_t* b) {
    asm volatile(
        "mma.sync.aligned.m16n8k8.row.col.f32.tf32.tf32.f32 "
        "{%0,%1,%2,%3}, {%4,%5,%6,%7}, {%8,%9}, {%0,%1,%2,%3};"
        : "+f"(c[0]), "+f"(c[1]), "+f"(c[2]), "+f"(c[3])
        : "r"(a[0]), "r"(a[1]), "r"(a[2]), "r"(a[3]), "r"(b[0]), "r"(b[1]));
}
__device__ __forceinline__ float bspline_c(float xv, int c, float g0, float invh) {
    float t = (xv - g0) * invh;
    float fj = floorf(t);
    float u = t - fj;
    int d = (int)fj - c;
    float v;
    if (d == 0)      v = u * u * u * (1.0f / 6.0f);
    else if (d == 1) v = (1.0f + 3.0f * u + 3.0f * u * u - 3.0f * u * u * u) * (1.0f / 6.0f);
    else if (d == 2) { float w = 1.0f - u; v = (1.0f + 3.0f * w + 3.0f * w * w - 3.0f * w * w * w) * (1.0f / 6.0f); }
    else if (d == 3) { float w = 1.0f - u; v = w * w * w * (1.0f / 6.0f); }
    else             v = 0.0f;
    return v;
}

// ---------------- prep kernels ----------------
__global__ void prep_grid(const float* __restrict__ grid) {
    if (threadIdx.x == 0) {
        g_gp[0] = grid[0];
        g_gp[1] = 1.0f / (grid[1] - grid[0]);
    }
}

// Split layout: [kc][o:128][kk:32].  fp32 layout: [k][o] with k=i | 128+c*128+i.
__global__ void prep_weights(const float* __restrict__ base_w,
                             const float* __restrict__ spline_w,
                             const float* __restrict__ scaler,
                             float* __restrict__ Wh, float* __restrict__ Wl,
                             float* __restrict__ Wf) {
    int idx = blockIdx.x * blockDim.x + threadIdx.x;
    if (idx >= HIDDEN * HIDDEN) return;
    int o = idx >> 7, i = idx & 127;
    int kk = i & 31;
    uint32_t hb, lb;
    float bw = base_w[o * HIDDEN + i];
    tf32_split(bw, hb, lb);
    int kc = i >> 5;
    ((uint32_t*)Wh)[kc * 4096 + o * 32 + kk] = hb;
    ((uint32_t*)Wl)[kc * 4096 + o * 32 + kk] = lb;
    Wf[(size_t)i * HIDDEN + o] = bw;
    float sc = scaler[o * HIDDEN + i];
#pragma unroll
    for (int c = 0; c < NCOEF; c++) {
        float w = spline_w[(o * HIDDEN + i) * NCOEF + c] * sc;
        tf32_split(w, hb, lb);
        int kc2 = 4 + c * 4 + (i >> 5);
        ((uint32_t*)Wh)[kc2 * 4096 + o * 32 + kk] = hb;
        ((uint32_t*)Wl)[kc2 * 4096 + o * 32 + kk] = lb;
        Wf[(size_t)(HIDDEN + c * HIDDEN + i) * HIDDEN + o] = w;
    }
}

__global__ void prep_protos(const float* __restrict__ protos) {
    int w = (blockIdx.x * blockDim.x + threadIdx.x) >> 5;
    int lane = threadIdx.x & 31;
    if (w >= NPROTO) return;
    float ss = 0.f;
    for (int i = lane; i < HIDDEN; i += 32) {
        float v = protos[w * HIDDEN + i];
        ss += v * v;
    }
#pragma unroll
    for (int off = 16; off; off >>= 1) ss += __shfl_xor_sync(0xffffffffu, ss, off);
    float inv = 1.0f / fmaxf(sqrtf(ss), 1e-8f);
    for (int i = lane; i < HIDDEN; i += 32) {
        float v = protos[w * HIDDEN + i] * inv;
        g_pn[w * HIDDEN + i] = v;
        g_pnT[i * NPROTO + w] = v;
    }
}

__global__ void reset_cnt() { g_cnt = 0; }

// ---------------- fused KAN layer: closed-form expansion + 3xTF32 mma.sync ----------------
#define SA_OFF  16384
#define SAL_OFF (SA_OFF + 4608)
#define SB_OFF  (SAL_OFF + 4608)
#define SBL_OFF (SB_OFF + 4608)
#define SM_FLOATS (SBL_OFF + 4608)

__global__ void __launch_bounds__(256, 1)
kan_tc(const float* __restrict__ in,
       const float* __restrict__ Wh, const float* __restrict__ Wl,
       float* __restrict__ out) {
    extern __shared__ float sm[];
    float* xs = sm;
    uint32_t* sAh = (uint32_t*)(sm + SA_OFF);
    uint32_t* sAl = (uint32_t*)(sm + SAL_OFF);
    uint32_t* sBh = (uint32_t*)(sm + SB_OFF);
    uint32_t* sBl = (uint32_t*)(sm + SBL_OFF);

    const int tid  = threadIdx.x;
    const int lane = tid & 31;
    const int wid  = tid >> 5;
    const int wr   = wid >> 2;
    const int wc   = wid & 3;
    const int gq   = lane >> 2;
    const int tq   = lane & 3;

    const float g0 = g_gp[0], invh = g_gp[1];
    const int m0 = blockIdx.x * TILE_M;

    {
        const float4* src = (const float4*)(in + (size_t)m0 * HIDDEN);
        float4* dst = (float4*)xs;
#pragma unroll
        for (int j = 0; j < 16; j++) dst[tid + j * 256] = src[tid + j * 256];
    }

    float acc[4][4][4];
#pragma unroll
    for (int a = 0; a < 4; a++)
#pragma unroll
        for (int b = 0; b < 4; b++)
#pragma unroll
            for (int c = 0; c < 4; c++) acc[a][b][c] = 0.f;

    for (int kc = 0; kc < NCHUNK; kc++) {
        __syncthreads();

        {
            const float4* sh = (const float4*)(Wh + kc * 4096);
            const float4* sl = (const float4*)(Wl + kc * 4096);
#pragma unroll
            for (int j = 0; j < 4; j++) {
                int f = tid + j * 256;
                int n = f >> 3, k4 = f & 7;
                ((float4*)sBh)[n * 9 + k4] = sh[f];
                ((float4*)sBl)[n * 9 + k4] = sl[f];
            }
        }

        {
            const bool is_silu = kc < 4;
            int c = 0, ibase;
            if (is_silu) ibase = kc * 32;
            else { int g = kc - 4; c = g >> 2; ibase = (g & 3) * 32; }
#pragma unroll
            for (int j = 0; j < 16; j++) {
                int e = tid + j * 256;
                int r = e >> 5, kk = e & 31;
                float xv = xs[r * HIDDEN + ibase + kk];
                float v;
                if (is_silu) v = xv / (1.0f + __expf(-xv));
                else         v = bspline_c(xv, c, g0, invh);
                uint32_t hb, lb;
                tf32_split(v, hb, lb);
                sAh[r * 36 + kk] = hb;
                sAl[r * 36 + kk] = lb;
            }
        }
        __syncthreads();

#pragma unroll
        for (int ks = 0; ks < 4; ks++) {
            uint32_t bh[4][2], bl[4][2];
#pragma unroll
            for (int nf = 0; nf < 4; nf++) {
                int col = wc * 32 + nf * 8 + gq;
                int kr  = ks * 8 + tq;
                bh[nf][0] = sBh[col * 36 + kr];
                bh[nf][1] = sBh[col * 36 + kr + 4];
                bl[nf][0] = sBl[col * 36 + kr];
                bl[nf][1] = sBl[col * 36 + kr + 4];
            }
#pragma unroll
            for (int mf = 0; mf < 4; mf++) {
                int row = wr * 64 + mf * 16 + gq;
                int kcol = ks * 8 + tq;
                uint32_t ah[4] = { sAh[row * 36 + kcol], sAh[(row + 8) * 36 + kcol],
                                   sAh[row * 36 + kcol + 4], sAh[(row + 8) * 36 + kcol + 4] };
                uint32_t al[4] = { sAl[row * 36 + kcol], sAl[(row + 8) * 36 + kcol],
                                   sAl[row * 36 + kcol + 4], sAl[(row + 8) * 36 + kcol + 4] };
#pragma unroll
                for (int nf = 0; nf < 4; nf++) {
                    mma8(acc[mf][nf], ah, bh[nf]);
                    mma8(acc[mf][nf], ah, bl[nf]);
                    mma8(acc[mf][nf], al, bh[nf]);
                }
            }
        }
    }

#pragma unroll
    for (int mf = 0; mf < 4; mf++) {
        int row = m0 + wr * 64 + mf * 16 + gq;
#pragma unroll
        for (int nf = 0; nf < 4; nf++) {
            int col = wc * 32 + nf * 8 + tq * 2;
            *(float2*)(out + (size_t)row * HIDDEN + col) =
                make_float2(acc[mf][nf][0], acc[mf][nf][1]);
            *(float2*)(out + (size_t)(row + 8) * HIDDEN + col) =
                make_float2(acc[mf][nf][2], acc[mf][nf][3]);
        }
    }
}

// ---------------- cosine argmax + near-tie flagging ----------------
__global__ void __launch_bounds__(256, 1)
cluster_kernel(const float* __restrict__ emb, float* __restrict__ assignOut) {
    extern __shared__ float sm[];
    float* sPn  = sm;                      // [256][129]
    float* sRow = sm + NPROTO * 129;       // [4][128]
    __shared__ float sV1[8][4], sV2[8][4];
    __shared__ int   sI1[8][4];

    int tid = threadIdx.x;
    for (int l = tid; l < NPROTO * HIDDEN; l += 256) {
        int k = l >> 7, i = l & 127;
        sPn[k * 129 + i] = g_pn[l];
    }
    __syncthreads();

    int base = blockIdx.x * RPB;
    for (int r0 = 0; r0 < RPB; r0 += 4) {
        for (int l = tid; l < 4 * HIDDEN; l += 256)
            sRow[l] = emb[(size_t)(base + r0) * HIDDEN + l];
        __syncthreads();

        float d0 = 0.f, d1 = 0.f, d2 = 0.f, d3 = 0.f;
        const float* pk = sPn + tid * 129;
#pragma unroll 8
        for (int i = 0; i < HIDDEN; i++) {
            float w = pk[i];
            d0 += sRow[i] * w;
            d1 += sRow[128 + i] * w;
            d2 += sRow[256 + i] * w;
            d3 += sRow[384 + i] * w;
        }
        float dv[4] = {d0, d1, d2, d3};
#pragma unroll
        for (int j = 0; j < 4; j++) {
            float v1 = dv[j]; int i1 = tid; float v2 = -1e30f;
#pragma unroll
            for (int off = 16; off; off >>= 1) {
                float ov1 = __shfl_down_sync(0xffffffffu, v1, off);
                int   oi1 = __shfl_down_sync(0xffffffffu, i1, off);
                float ov2 = __shfl_down_sync(0xffffffffu, v2, off);
                if (ov1 > v1 || (ov1 == v1 && oi1 < i1)) {
                    v2 = fmaxf(v1, ov2); v1 = ov1; i1 = oi1;
                } else {
                    v2 = fmaxf(v2, ov1);
                }
            }
            if ((tid & 31) == 0) { sV1[tid >> 5][j] = v1; sI1[tid >> 5][j] = i1; sV2[tid >> 5][j] = v2; }
        }
        __syncthreads();
        if (tid < 4) {
            float v1 = sV1[0][tid]; int i1 = sI1[0][tid]; float v2 = sV2[0][tid];
#pragma unroll
            for (int w = 1; w < 8; w++) {
                float ov1 = sV1[w][tid]; int oi1 = sI1[w][tid]; float ov2 = sV2[w][tid];
                if (ov1 > v1 || (ov1 == v1 && oi1 < i1)) {
                    v2 = fmaxf(v1, ov2); v1 = ov1; i1 = oi1;
                } else {
                    v2 = fmaxf(v2, ov1);
                }
            }
            int row = base + r0 + tid;
            assignOut[row] = (float)i1;
            if (v1 - v2 < TAU) {
                int s = atomicAdd(&g_cnt, 1);
                g_list[s] = row;
            }
        }
        __syncthreads();
    }
}

// ---------------- fp32 fixup: recompute flagged rows end-to-end ----------------
// smem: A[32][1152] | hb[32][128] | ws[32][128]
__global__ void __launch_bounds__(256, 1)
fixup_kernel(const float* __restrict__ x,
             const float* __restrict__ Wf1, const float* __restrict__ Wf2,
             float* __restrict__ assignOut) {
    extern __shared__ float sm[];
    float* A  = sm;                 // 36864
    float* hb = sm + 36864;         // 4096
    float* ws = sm + 40960;         // 4096
    __shared__ int ridx[32];
    __shared__ float rv[8];
    __shared__ int   rp[8];

    const int tid = threadIdx.x;
    const int start = blockIdx.x * 32;
    const int cnt = g_cnt;
    if (start >= cnt) return;
    const int nr = min(32, cnt - start);
    if (tid < 32) {
        int src = start + (tid < nr ? tid : nr - 1);
        ridx[tid] = g_list[src];
    }
    __syncthreads();

    const float g0 = g_gp[0], invh = g_gp[1];
    const int tr = tid >> 5;
    const int tc = tid & 31;

    float acc[4][4];
    const float* Wf = Wf1;
    const float* src = x;
    bool gather = true;

    for (int layer = 0; layer < 2; layer++) {
        // ---- expansion into A ----
        for (int e = tid; e < 32 * HIDDEN; e += 256) {
            int r = e >> 7, i = e & 127;
            float xv = gather ? src[(size_t)ridx[r] * HIDDEN + i] : src[r * HIDDEN + i];
            A[r * KDIM + i] = xv / (1.0f + __expf(-xv));
#pragma unroll
            for (int c = 0; c < NCOEF; c++)
                A[r * KDIM + HIDDEN + c * HIDDEN + i] = bspline_c(xv, c, g0, invh);
        }

        // ---- GEMM [32x1152]@[1152x128] ----
#pragma unroll
        for (int a = 0; a < 4; a++)
#pragma unroll
            for (int b = 0; b < 4; b++) acc[a][b] = 0.f;

        for (int k0 = 0; k0 < KDIM; k0 += 32) {
            __syncthreads();
            const float4* gw = (const float4*)(Wf + (size_t)k0 * HIDDEN);
#pragma unroll
            for (int l = 0; l < 4; l++)
                ((float4*)ws)[tid + l * 256] = gw[tid + l * 256];
            __syncthreads();
#pragma unroll
            for (int kk = 0; kk < 32; kk++) {
                float a0 = A[(tr * 4 + 0) * KDIM + k0 + kk];
                float a1 = A[(tr * 4 + 1) * KDIM + k0 + kk];
                float a2 = A[(tr * 4 + 2) * KDIM + k0 + kk];
                float a3 = A[(tr * 4 + 3) * KDIM + k0 + kk];
                float4 w = ((float4*)ws)[kk * 32 + tc];
                acc[0][0] += a0 * w.x; acc[0][1] += a0 * w.y; acc[0][2] += a0 * w.z; acc[0][3] += a0 * w.w;
                acc[1][0] += a1 * w.x; acc[1][1] += a1 * w.y; acc[1][2] += a1 * w.z; acc[1][3] += a1 * w.w;
                acc[2][0] += a2 * w.x; acc[2][1] += a2 * w.y; acc[2][2] += a2 * w.z; acc[2][3] += a2 * w.w;
                acc[3][0] += a3 * w.x; acc[3][1] += a3 * w.y; acc[3][2] += a3 * w.z; acc[3][3] += a3 * w.w;
            }
        }
        __syncthreads();
#pragma unroll
        for (int ri = 0; ri < 4; ri++)
            ((float4*)(hb + (tr * 4 + ri) * HIDDEN))[tc] =
                make_float4(acc[ri][0], acc[ri][1], acc[ri][2], acc[ri][3]);
        __syncthreads();

        Wf = Wf2; src = hb; gather = false;
    }

    // ---- sims vs normalized prototypes (argmax scale-invariant) ----
    float sims[32];
#pragma unroll
    for (int r = 0; r < 32; r++) sims[r] = 0.f;
    for (int i = 0; i < HIDDEN; i++) {
        float pv = g_pnT[i * NPROTO + tid];
#pragma unroll
        for (int r = 0; r < 32; r++) sims[r] += hb[r * HIDDEN + i] * pv;
    }

    for (int r = 0; r < 32; r++) {
        float v = sims[r]; int bi = tid;
#pragma unroll
        for (int off = 16; off; off >>= 1) {
            float ov = __shfl_down_sync(0xffffffffu, v, off);
            int   oi = __shfl_down_sync(0xffffffffu, bi, off);
            if (ov > v || (ov == v && oi < bi)) { v = ov; bi = oi; }
        }
        if ((tid & 31) == 0) { rv[tid >> 5] = v; rp[tid >> 5] = bi; }
        __syncthreads();
        if (tid == 0) {
            float bv = rv[0]; int bb = rp[0];
#pragma unroll
            for (int w = 1; w < 8; w++)
                if (rv[w] > bv || (rv[w] == bv && rp[w] < bb)) { bv = rv[w]; bb = rp[w]; }
            if (r < nr) assignOut[ridx[r]] = (float)bb;
        }
        __syncthreads();
    }
}

// ---------------- launch ----------------
extern "C" void kernel_launch(void* const* d_in, const int* in_sizes, int n_in,
                              void* d_out, int out_size) {
    const float* x         = (const float*)d_in[0];
    const float* protos    = (const float*)d_in[1];
    const float* grid      = (const float*)d_in[2];
    const float* base_w1   = (const float*)d_in[3];
    const float* spline_w1 = (const float*)d_in[4];
    const float* scaler1   = (const float*)d_in[5];
    const float* base_w2   = (const float*)d_in[6];
    const float* spline_w2 = (const float*)d_in[7];
    const float* scaler2   = (const float*)d_in[8];

    int n = in_sizes[0] / HIDDEN;

    float *Wh1, *Wl1, *Wh2, *Wl2, *Wf1, *Wf2, *h;
    cudaGetSymbolAddress((void**)&Wh1, g_Wh1);
    cudaGetSymbolAddress((void**)&Wl1, g_Wl1);
    cudaGetSymbolAddress((void**)&Wh2, g_Wh2);
    cudaGetSymbolAddress((void**)&Wl2, g_Wl2);
    cudaGetSymbolAddress((void**)&Wf1, g_Wf1);
    cudaGetSymbolAddress((void**)&Wf2, g_Wf2);
    cudaGetSymbolAddress((void**)&h,  g_h);

    prep_grid<<<1, 32>>>(grid);                                              // 0
    prep_protos<<<32, 256>>>(protos);                                        // 1
    prep_weights<<<64, 256>>>(base_w1, spline_w1, scaler1, Wh1, Wl1, Wf1);   // 2
    prep_weights<<<64, 256>>>(base_w2, spline_w2, scaler2, Wh2, Wl2, Wf2);   // 3

    size_t smemL = SM_FLOATS * sizeof(float);
    cudaFuncSetAttribute(kan_tc, cudaFuncAttributeMaxDynamicSharedMemorySize, (int)smemL);

    float* emb = (float*)d_out;
    kan_tc<<<n / TILE_M, 256, smemL>>>(x, Wh1, Wl1, h);                      // 4
    kan_tc<<<n / TILE_M, 256, smemL>>>(h, Wh2, Wl2, emb);                    // 5 (ncu -s 5)

    if (out_size >= n * HIDDEN + n) {
        float* assign = emb + (size_t)n * HIDDEN;
        reset_cnt<<<1, 32>>>();                                              // 6
        size_t smemC = (size_t)(NPROTO * 129 + 4 * HIDDEN) * sizeof(float);
        cudaFuncSetAttribute(cluster_kernel, cudaFuncAttributeMaxDynamicSharedMemorySize, (int)smemC);
        cluster_kernel<<<n / RPB, 256, smemC>>>(emb, assign);                // 7
        size_t smemF = 45056 * sizeof(float);
        cudaFuncSetAttribute(fixup_kernel, cudaFuncAttributeMaxDynamicSharedMemorySize, (int)smemF);
        fixup_kernel<<<(n + 31) / 32, 256, smemF>>>(x, Wf1, Wf2, assign);    // 8
    }
}

// round 6
// speedup vs baseline: 1.5751x; 1.5751x over previous
#include <cuda_runtime.h>
#include <cuda_fp16.h>
#include <cstdint>

#define HIDDEN 128
#define NCOEF  8
#define NPROTO 256
#define NMAX   131072
#define RPB    64
#define TILE_M 128
#define NCHUNK 36            // 1152 / 32
#define KDIM   1152
#define TAU    4e-4f
#define NTHR   512

// ---------------- device scratch ----------------
// packed half2 weights: [kc][n:128][kp:16] uint32
__device__ uint32_t g_Wh1[NCHUNK * 2048];
__device__ uint32_t g_Wl1[NCHUNK * 2048];
__device__ uint32_t g_Wh2[NCHUNK * 2048];
__device__ uint32_t g_Wl2[NCHUNK * 2048];
__device__ float g_Wf1[KDIM * HIDDEN];     // fp32 combined, [k][o] (fixup)
__device__ float g_Wf2[KDIM * HIDDEN];
__device__ float g_h[(size_t)NMAX * HIDDEN];
__device__ float g_pn[NPROTO * HIDDEN];
__device__ float g_pnT[HIDDEN * NPROTO];
__device__ float g_gp[2];                  // g0, invh
__device__ int   g_cnt;
__device__ int   g_list[NMAX];

// ---------------- helpers ----------------
__device__ __forceinline__ uint32_t h2_split_hi(float v0, float v1, uint32_t& lo_out) {
    __half h0 = __float2half_rn(v0);
    __half h1 = __float2half_rn(v1);
    __half l0 = __float2half_rn(v0 - __half2float(h0));
    __half l1 = __float2half_rn(v1 - __half2float(h1));
    __half2 hp = __halves2half2(h0, h1);
    __half2 lp = __halves2half2(l0, l1);
    lo_out = *(uint32_t*)&lp;
    return *(uint32_t*)&hp;
}
__device__ __forceinline__ void mma16(float* c, const uint32_t* a, const uint32_t* b) {
    asm volatile(
        "mma.sync.aligned.m16n8k16.row.col.f32.f16.f16.f32 "
        "{%0,%1,%2,%3}, {%4,%5,%6,%7}, {%8,%9}, {%0,%1,%2,%3};"
        : "+f"(c[0]), "+f"(c[1]), "+f"(c[2]), "+f"(c[3])
        : "r"(a[0]), "r"(a[1]), "r"(a[2]), "r"(a[3]), "r"(b[0]), "r"(b[1]));
}
__device__ __forceinline__ float bspline_c(float xv, int c, float g0, float invh) {
    float t = (xv - g0) * invh;
    float fj = floorf(t);
    float u = t - fj;
    int d = (int)fj - c;
    float v;
    if (d == 0)      v = u * u * u * (1.0f / 6.0f);
    else if (d == 1) v = (1.0f + 3.0f * u + 3.0f * u * u - 3.0f * u * u * u) * (1.0f / 6.0f);
    else if (d == 2) { float w = 1.0f - u; v = (1.0f + 3.0f * w + 3.0f * w * w - 3.0f * w * w * w) * (1.0f / 6.0f); }
    else if (d == 3) { float w = 1.0f - u; v = w * w * w * (1.0f / 6.0f); }
    else             v = 0.0f;
    return v;
}

// ---------------- prep kernels ----------------
__global__ void prep_grid(const float* __restrict__ grid) {
    if (threadIdx.x == 0) {
        g_gp[0] = grid[0];
        g_gp[1] = 1.0f / (grid[1] - grid[0]);
    }
}

// threads over o(128) x m(64 i-pairs). i0=2m, i1=2m+1; iq=m>>4; kp=m&15.
// silu block: kc=iq.  spline c: kc=4+c*4+iq.
__global__ void prep_weights(const float* __restrict__ base_w,
                             const float* __restrict__ spline_w,
                             const float* __restrict__ scaler,
                             uint32_t* __restrict__ Wh, uint32_t* __restrict__ Wl,
                             float* __restrict__ Wf) {
    int idx = blockIdx.x * blockDim.x + threadIdx.x;
    if (idx >= HIDDEN * 64) return;
    int o = idx >> 6, m = idx & 63;
    int i0 = 2 * m, i1 = 2 * m + 1;
    int iq = m >> 4, kp = m & 15;

    float w0 = base_w[o * HIDDEN + i0];
    float w1 = base_w[o * HIDDEN + i1];
    uint32_t lo, hi = h2_split_hi(w0, w1, lo);
    Wh[iq * 2048 + o * 16 + kp] = hi;
    Wl[iq * 2048 + o * 16 + kp] = lo;
    Wf[(size_t)i0 * HIDDEN + o] = w0;
    Wf[(size_t)i1 * HIDDEN + o] = w1;

    float sc0 = scaler[o * HIDDEN + i0];
    float sc1 = scaler[o * HIDDEN + i1];
#pragma unroll
    for (int c = 0; c < NCOEF; c++) {
        float s0 = spline_w[(o * HIDDEN + i0) * NCOEF + c] * sc0;
        float s1 = spline_w[(o * HIDDEN + i1) * NCOEF + c] * sc1;
        hi = h2_split_hi(s0, s1, lo);
        int kc = 4 + c * 4 + iq;
        Wh[kc * 2048 + o * 16 + kp] = hi;
        Wl[kc * 2048 + o * 16 + kp] = lo;
        Wf[(size_t)(HIDDEN + c * HIDDEN + i0) * HIDDEN + o] = s0;
        Wf[(size_t)(HIDDEN + c * HIDDEN + i1) * HIDDEN + o] = s1;
    }
}

__global__ void prep_protos(const float* __restrict__ protos) {
    int w = (blockIdx.x * blockDim.x + threadIdx.x) >> 5;
    int lane = threadIdx.x & 31;
    if (w >= NPROTO) return;
    float ss = 0.f;
    for (int i = lane; i < HIDDEN; i += 32) {
        float v = protos[w * HIDDEN + i];
        ss += v * v;
    }
#pragma unroll
    for (int off = 16; off; off >>= 1) ss += __shfl_xor_sync(0xffffffffu, ss, off);
    float inv = 1.0f / fmaxf(sqrtf(ss), 1e-8f);
    for (int i = lane; i < HIDDEN; i += 32) {
        float v = protos[w * HIDDEN + i] * inv;
        g_pn[w * HIDDEN + i] = v;
        g_pnT[i * NPROTO + w] = v;
    }
}

__global__ void reset_cnt() { g_cnt = 0; }

// ---------------- fused KAN layer: fp16 2-split 3-term m16n8k16 ----------------
// smem (u32 view): xs[16384 f] | sAh[128*20] | sAl | sBh[128*20] | sBl   (stride 20 = conflict-free)
#define U_SAH 16384
#define U_SAL (U_SAH + 2560)
#define U_SBH (U_SAL + 2560)
#define U_SBL (U_SBH + 2560)
#define SM_WORDS (U_SBL + 2560)      // 26624 u32 = 106496 B

__global__ void __launch_bounds__(NTHR, 1)
kan_tc(const float* __restrict__ in,
       const uint32_t* __restrict__ Wh, const uint32_t* __restrict__ Wl,
       float* __restrict__ out) {
    extern __shared__ float sm[];
    float* xs = sm;
    uint32_t* sAh = (uint32_t*)sm + U_SAH;
    uint32_t* sAl = (uint32_t*)sm + U_SAL;
    uint32_t* sBh = (uint32_t*)sm + U_SBH;
    uint32_t* sBl = (uint32_t*)sm + U_SBL;

    const int tid  = threadIdx.x;
    const int lane = tid & 31;
    const int wid  = tid >> 5;        // 0..15
    const int wr   = wid >> 2;        // 0..3  rows wr*32
    const int wc   = wid & 3;         // 0..3  cols wc*32
    const int gq   = lane >> 2;       // 0..7
    const int tq   = lane & 3;        // 0..3

    const float g0 = g_gp[0], invh = g_gp[1];
    const int m0 = blockIdx.x * TILE_M;

    {   // 16384 floats / 512 thr = 8 float4
        const float4* src = (const float4*)(in + (size_t)m0 * HIDDEN);
        float4* dst = (float4*)xs;
#pragma unroll
        for (int j = 0; j < 8; j++) dst[tid + j * NTHR] = src[tid + j * NTHR];
    }

    float acc[2][4][4];
#pragma unroll
    for (int a = 0; a < 2; a++)
#pragma unroll
        for (int b = 0; b < 4; b++)
#pragma unroll
            for (int c = 0; c < 4; c++) acc[a][b][c] = 0.f;

    for (int kc = 0; kc < NCHUNK; kc++) {
        __syncthreads();

        // ---- B chunk copy: [n][kp] (16) -> smem stride 20; uint2 per thread x2 ----
        {
            const uint2* sh = (const uint2*)(Wh + kc * 2048);
            const uint2* sl = (const uint2*)(Wl + kc * 2048);
#pragma unroll
            for (int j = 0; j < 2; j++) {
                int f2 = tid + j * NTHR;          // 0..1023
                int n = f2 >> 3, kp2 = f2 & 7;
                ((uint2*)(sBh + n * 20))[kp2] = sh[f2];
                ((uint2*)(sBl + n * 20))[kp2] = sl[f2];
            }
        }

        // ---- A chunk expansion: 2048 pairs / 512 thr = 4 ----
        {
            const bool is_silu = kc < 4;
            int c = 0, ibase;
            if (is_silu) ibase = kc * 32;
            else { int g = kc - 4; c = g >> 2; ibase = (g & 3) * 32; }
#pragma unroll
            for (int j = 0; j < 4; j++) {
                int p = tid + j * NTHR;           // pair id
                int r = p >> 4, kp = p & 15;
                float2 xv = *(const float2*)(xs + r * HIDDEN + ibase + 2 * kp);
                float v0, v1;
                if (is_silu) {
                    v0 = xv.x / (1.0f + __expf(-xv.x));
                    v1 = xv.y / (1.0f + __expf(-xv.y));
                } else {
                    v0 = bspline_c(xv.x, c, g0, invh);
                    v1 = bspline_c(xv.y, c, g0, invh);
                }
                uint32_t lo, hi = h2_split_hi(v0, v1, lo);
                sAh[r * 20 + kp] = hi;
                sAl[r * 20 + kp] = lo;
            }
        }
        __syncthreads();

        // ---- warp MMA: 3-term fp16, 2x k16 steps ----
#pragma unroll
        for (int ks = 0; ks < 2; ks++) {
            const int kb = ks * 8 + tq;
            uint32_t bh[4][2], bl[4][2];
#pragma unroll
            for (int nf = 0; nf < 4; nf++) {
                int col = wc * 32 + nf * 8 + gq;
                bh[nf][0] = sBh[col * 20 + kb];
                bh[nf][1] = sBh[col * 20 + kb + 4];
                bl[nf][0] = sBl[col * 20 + kb];
                bl[nf][1] = sBl[col * 20 + kb + 4];
            }
#pragma unroll
            for (int mf = 0; mf < 2; mf++) {
                int row = wr * 32 + mf * 16 + gq;
                uint32_t ah[4] = { sAh[row * 20 + kb], sAh[(row + 8) * 20 + kb],
                                   sAh[row * 20 + kb + 4], sAh[(row + 8) * 20 + kb + 4] };
                uint32_t al[4] = { sAl[row * 20 + kb], sAl[(row + 8) * 20 + kb],
                                   sAl[row * 20 + kb + 4], sAl[(row + 8) * 20 + kb + 4] };
#pragma unroll
                for (int nf = 0; nf < 4; nf++) {
                    mma16(acc[mf][nf], ah, bh[nf]);
                    mma16(acc[mf][nf], ah, bl[nf]);
                    mma16(acc[mf][nf], al, bh[nf]);
                }
            }
        }
    }

    // ---- epilogue: c0,c1 @ (row, 2tq..), c2,c3 @ (row+8, 2tq..) ----
#pragma unroll
    for (int mf = 0; mf < 2; mf++) {
        int row = m0 + wr * 32 + mf * 16 + gq;
#pragma unroll
        for (int nf = 0; nf < 4; nf++) {
            int col = wc * 32 + nf * 8 + tq * 2;
            *(float2*)(out + (size_t)row * HIDDEN + col) =
                make_float2(acc[mf][nf][0], acc[mf][nf][1]);
            *(float2*)(out + (size_t)(row + 8) * HIDDEN + col) =
                make_float2(acc[mf][nf][2], acc[mf][nf][3]);
        }
    }
}

// ---------------- cosine argmax + near-tie flagging ----------------
__global__ void __launch_bounds__(256, 1)
cluster_kernel(const float* __restrict__ emb, float* __restrict__ assignOut) {
    extern __shared__ float sm[];
    float* sPn  = sm;                      // [256][129]
    float* sRow = sm + NPROTO * 129;       // [4][128]
    __shared__ float sV1[8][4], sV2[8][4];
    __shared__ int   sI1[8][4];

    int tid = threadIdx.x;
    for (int l = tid; l < NPROTO * HIDDEN; l += 256) {
        int k = l >> 7, i = l & 127;
        sPn[k * 129 + i] = g_pn[l];
    }
    __syncthreads();

    int base = blockIdx.x * RPB;
    for (int r0 = 0; r0 < RPB; r0 += 4) {
        for (int l = tid; l < 4 * HIDDEN; l += 256)
            sRow[l] = emb[(size_t)(base + r0) * HIDDEN + l];
        __syncthreads();

        float d0 = 0.f, d1 = 0.f, d2 = 0.f, d3 = 0.f;
        const float* pk = sPn + tid * 129;
#pragma unroll 8
        for (int i = 0; i < HIDDEN; i++) {
            float w = pk[i];
            d0 += sRow[i] * w;
            d1 += sRow[128 + i] * w;
            d2 += sRow[256 + i] * w;
            d3 += sRow[384 + i] * w;
        }
        float dv[4] = {d0, d1, d2, d3};
#pragma unroll
        for (int j = 0; j < 4; j++) {
            float v1 = dv[j]; int i1 = tid; float v2 = -1e30f;
#pragma unroll
            for (int off = 16; off; off >>= 1) {
                float ov1 = __shfl_down_sync(0xffffffffu, v1, off);
                int   oi1 = __shfl_down_sync(0xffffffffu, i1, off);
                float ov2 = __shfl_down_sync(0xffffffffu, v2, off);
                if (ov1 > v1 || (ov1 == v1 && oi1 < i1)) {
                    v2 = fmaxf(v1, ov2); v1 = ov1; i1 = oi1;
                } else {
                    v2 = fmaxf(v2, ov1);
                }
            }
            if ((tid & 31) == 0) { sV1[tid >> 5][j] = v1; sI1[tid >> 5][j] = i1; sV2[tid >> 5][j] = v2; }
        }
        __syncthreads();
        if (tid < 4) {
            float v1 = sV1[0][tid]; int i1 = sI1[0][tid]; float v2 = sV2[0][tid];
#pragma unroll
            for (int w = 1; w < 8; w++) {
                float ov1 = sV1[w][tid]; int oi1 = sI1[w][tid]; float ov2 = sV2[w][tid];
                if (ov1 > v1 || (ov1 == v1 && oi1 < i1)) {
                    v2 = fmaxf(v1, ov2); v1 = ov1; i1 = oi1;
                } else {
                    v2 = fmaxf(v2, ov1);
                }
            }
            int row = base + r0 + tid;
            assignOut[row] = (float)i1;
            if (v1 - v2 < TAU) {
                int s = atomicAdd(&g_cnt, 1);
                g_list[s] = row;
            }
        }
        __syncthreads();
    }
}

// ---------------- fp32 fixup: recompute flagged rows end-to-end ----------------
__global__ void __launch_bounds__(256, 1)
fixup_kernel(const float* __restrict__ x,
             const float* __restrict__ Wf1, const float* __restrict__ Wf2,
             float* __restrict__ assignOut) {
    extern __shared__ float sm[];
    float* A  = sm;                 // 36864
    float* hb = sm + 36864;         // 4096
    float* ws = sm + 40960;         // 4096
    __shared__ int ridx[32];
    __shared__ float rv[8];
    __shared__ int   rp[8];

    const int tid = threadIdx.x;
    const int start = blockIdx.x * 32;
    const int cnt = g_cnt;
    if (start >= cnt) return;
    const int nr = min(32, cnt - start);
    if (tid < 32) {
        int srci = start + (tid < nr ? tid : nr - 1);
        ridx[tid] = g_list[srci];
    }
    __syncthreads();

    const float g0 = g_gp[0], invh = g_gp[1];
    const int tr = tid >> 5;
    const int tc = tid & 31;

    float acc[4][4];
    const float* Wf = Wf1;
    const float* src = x;
    bool gather = true;

    for (int layer = 0; layer < 2; layer++) {
        for (int e = tid; e < 32 * HIDDEN; e += 256) {
            int r = e >> 7, i = e & 127;
            float xv = gather ? src[(size_t)ridx[r] * HIDDEN + i] : src[r * HIDDEN + i];
            A[r * KDIM + i] = xv / (1.0f + __expf(-xv));
#pragma unroll
            for (int c = 0; c < NCOEF; c++)
                A[r * KDIM + HIDDEN + c * HIDDEN + i] = bspline_c(xv, c, g0, invh);
        }

#pragma unroll
        for (int a = 0; a < 4; a++)
#pragma unroll
            for (int b = 0; b < 4; b++) acc[a][b] = 0.f;

        for (int k0 = 0; k0 < KDIM; k0 += 32) {
            __syncthreads();
            const float4* gw = (const float4*)(Wf + (size_t)k0 * HIDDEN);
#pragma unroll
            for (int l = 0; l < 4; l++)
                ((float4*)ws)[tid + l * 256] = gw[tid + l * 256];
            __syncthreads();
#pragma unroll
            for (int kk = 0; kk < 32; kk++) {
                float a0 = A[(tr * 4 + 0) * KDIM + k0 + kk];
                float a1 = A[(tr * 4 + 1) * KDIM + k0 + kk];
                float a2 = A[(tr * 4 + 2) * KDIM + k0 + kk];
                float a3 = A[(tr * 4 + 3) * KDIM + k0 + kk];
                float4 w = ((float4*)ws)[kk * 32 + tc];
                acc[0][0] += a0 * w.x; acc[0][1] += a0 * w.y; acc[0][2] += a0 * w.z; acc[0][3] += a0 * w.w;
                acc[1][0] += a1 * w.x; acc[1][1] += a1 * w.y; acc[1][2] += a1 * w.z; acc[1][3] += a1 * w.w;
                acc[2][0] += a2 * w.x; acc[2][1] += a2 * w.y; acc[2][2] += a2 * w.z; acc[2][3] += a2 * w.w;
                acc[3][0] += a3 * w.x; acc[3][1] += a3 * w.y; acc[3][2] += a3 * w.z; acc[3][3] += a3 * w.w;
            }
        }
        __syncthreads();
#pragma unroll
        for (int ri = 0; ri < 4; ri++)
            ((float4*)(hb + (tr * 4 + ri) * HIDDEN))[tc] =
                make_float4(acc[ri][0], acc[ri][1], acc[ri][2], acc[ri][3]);
        __syncthreads();

        Wf = Wf2; src = hb; gather = false;
    }

    float sims[32];
#pragma unroll
    for (int r = 0; r < 32; r++) sims[r] = 0.f;
    for (int i = 0; i < HIDDEN; i++) {
        float pv = g_pnT[i * NPROTO + tid];
#pragma unroll
        for (int r = 0; r < 32; r++) sims[r] += hb[r * HIDDEN + i] * pv;
    }

    for (int r = 0; r < 32; r++) {
        float v = sims[r]; int bi = tid;
#pragma unroll
        for (int off = 16; off; off >>= 1) {
            float ov = __shfl_down_sync(0xffffffffu, v, off);
            int   oi = __shfl_down_sync(0xffffffffu, bi, off);
            if (ov > v || (ov == v && oi < bi)) { v = ov; bi = oi; }
        }
        if ((tid & 31) == 0) { rv[tid >> 5] = v; rp[tid >> 5] = bi; }
        __syncthreads();
        if (tid == 0) {
            float bv = rv[0]; int bb = rp[0];
#pragma unroll
            for (int w = 1; w < 8; w++)
                if (rv[w] > bv || (rv[w] == bv && rp[w] < bb)) { bv = rv[w]; bb = rp[w]; }
            if (r < nr) assignOut[ridx[r]] = (float)bb;
        }
        __syncthreads();
    }
}

// ---------------- launch ----------------
extern "C" void kernel_launch(void* const* d_in, const int* in_sizes, int n_in,
                              void* d_out, int out_size) {
    const float* x         = (const float*)d_in[0];
    const float* protos    = (const float*)d_in[1];
    const float* grid      = (const float*)d_in[2];
    const float* base_w1   = (const float*)d_in[3];
    const float* spline_w1 = (const float*)d_in[4];
    const float* scaler1   = (const float*)d_in[5];
    const float* base_w2   = (const float*)d_in[6];
    const float* spline_w2 = (const float*)d_in[7];
    const float* scaler2   = (const float*)d_in[8];

    int n = in_sizes[0] / HIDDEN;

    uint32_t *Wh1, *Wl1, *Wh2, *Wl2;
    float *Wf1, *Wf2, *h;
    cudaGetSymbolAddress((void**)&Wh1, g_Wh1);
    cudaGetSymbolAddress((void**)&Wl1, g_Wl1);
    cudaGetSymbolAddress((void**)&Wh2, g_Wh2);
    cudaGetSymbolAddress((void**)&Wl2, g_Wl2);
    cudaGetSymbolAddress((void**)&Wf1, g_Wf1);
    cudaGetSymbolAddress((void**)&Wf2, g_Wf2);
    cudaGetSymbolAddress((void**)&h,  g_h);

    prep_grid<<<1, 32>>>(grid);                                              // 0
    prep_weights<<<32, 256>>>(base_w1, spline_w1, scaler1, Wh1, Wl1, Wf1);   // 1
    prep_weights<<<32, 256>>>(base_w2, spline_w2, scaler2, Wh2, Wl2, Wf2);   // 2

    size_t smemL = SM_WORDS * 4;
    cudaFuncSetAttribute(kan_tc, cudaFuncAttributeMaxDynamicSharedMemorySize, (int)smemL);

    float* emb = (float*)d_out;
    kan_tc<<<n / TILE_M, NTHR, smemL>>>(x, Wh1, Wl1, h);                     // 3  <- ncu capture
    kan_tc<<<n / TILE_M, NTHR, smemL>>>(h, Wh2, Wl2, emb);                   // 4

    if (out_size >= n * HIDDEN + n) {
        float* assign = emb + (size_t)n * HIDDEN;
        prep_protos<<<32, 256>>>(protos);                                    // 5
        reset_cnt<<<1, 32>>>();                                              // 6
        size_t smemC = (size_t)(NPROTO * 129 + 4 * HIDDEN) * sizeof(float);
        cudaFuncSetAttribute(cluster_kernel, cudaFuncAttributeMaxDynamicSharedMemorySize, (int)smemC);
        cluster_kernel<<<n / RPB, 256, smemC>>>(emb, assign);                // 7
        size_t smemF = 45056 * sizeof(float);
        cudaFuncSetAttribute(fixup_kernel, cudaFuncAttributeMaxDynamicSharedMemorySize, (int)smemF);
        fixup_kernel<<<(n + 31) / 32, 256, smemF>>>(x, Wf1, Wf2, assign);    // 8
    }
}

// round 8
// speedup vs baseline: 1.8633x; 1.1830x over previous
#include <cuda_runtime.h>
#include <cuda_fp16.h>
#include <cstdint>

#define HIDDEN 128
#define NCOEF  8
#define NPROTO 256
#define NMAX   131072
#define TILE_M 128
#define NCHUNK 36            // 1152 / 32
#define KDIM   1152
#define TAU    4e-4f
#define NTHR   512

// ---------------- device scratch ----------------
__device__ uint32_t g_Wh1[NCHUNK * 2048];
__device__ uint32_t g_Wl1[NCHUNK * 2048];
__device__ uint32_t g_Wh2[NCHUNK * 2048];
__device__ uint32_t g_Wl2[NCHUNK * 2048];
__device__ float g_Wf1[KDIM * HIDDEN];     // fp32 combined, [k][o] (fixup)
__device__ float g_Wf2[KDIM * HIDDEN];
__device__ float g_h[(size_t)NMAX * HIDDEN];
__device__ float g_pn[NPROTO * HIDDEN];
__device__ float g_pnT[HIDDEN * NPROTO];
__device__ float g_gp[2];                  // g0, invh
__device__ int   g_cnt;
__device__ int   g_list[NMAX];

// ---------------- helpers ----------------
__device__ __forceinline__ uint32_t h2_split_hi(float v0, float v1, uint32_t& lo_out) {
    __half h0 = __float2half_rn(v0);
    __half h1 = __float2half_rn(v1);
    __half l0 = __float2half_rn(v0 - __half2float(h0));
    __half l1 = __float2half_rn(v1 - __half2float(h1));
    __half2 hp = __halves2half2(h0, h1);
    __half2 lp = __halves2half2(l0, l1);
    lo_out = *(uint32_t*)&lp;
    return *(uint32_t*)&hp;
}
__device__ __forceinline__ void mma16(float* c, const uint32_t* a, const uint32_t* b) {
    asm volatile(
        "mma.sync.aligned.m16n8k16.row.col.f32.f16.f16.f32 "
        "{%0,%1,%2,%3}, {%4,%5,%6,%7}, {%8,%9}, {%0,%1,%2,%3};"
        : "+f"(c[0]), "+f"(c[1]), "+f"(c[2]), "+f"(c[3])
        : "r"(a[0]), "r"(a[1]), "r"(a[2]), "r"(a[3]), "r"(b[0]), "r"(b[1]));
}
__device__ __forceinline__ float bspline_c(float xv, int c, float g0, float invh) {
    float t = (xv - g0) * invh;
    float fj = floorf(t);
    float u = t - fj;
    int d = (int)fj - c;
    float v;
    if (d == 0)      v = u * u * u * (1.0f / 6.0f);
    else if (d == 1) v = (1.0f + 3.0f * u + 3.0f * u * u - 3.0f * u * u * u) * (1.0f / 6.0f);
    else if (d == 2) { float w = 1.0f - u; v = (1.0f + 3.0f * w + 3.0f * w * w - 3.0f * w * w * w) * (1.0f / 6.0f); }
    else if (d == 3) { float w = 1.0f - u; v = w * w * w * (1.0f / 6.0f); }
    else             v = 0.0f;
    return v;
}

// ---------------- prep kernels ----------------
__global__ void prep_grid(const float* __restrict__ grid) {
    if (threadIdx.x == 0) {
        g_gp[0] = grid[0];
        g_gp[1] = 1.0f / (grid[1] - grid[0]);
    }
}

__global__ void prep_weights(const float* __restrict__ base_w,
                             const float* __restrict__ spline_w,
                             const float* __restrict__ scaler,
                             uint32_t* __restrict__ Wh, uint32_t* __restrict__ Wl,
                             float* __restrict__ Wf) {
    int idx = blockIdx.x * blockDim.x + threadIdx.x;
    if (idx >= HIDDEN * 64) return;
    int o = idx >> 6, m = idx & 63;
    int i0 = 2 * m, i1 = 2 * m + 1;
    int iq = m >> 4, kp = m & 15;

    float w0 = base_w[o * HIDDEN + i0];
    float w1 = base_w[o * HIDDEN + i1];
    uint32_t lo, hi = h2_split_hi(w0, w1, lo);
    Wh[iq * 2048 + o * 16 + kp] = hi;
    Wl[iq * 2048 + o * 16 + kp] = lo;
    Wf[(size_t)i0 * HIDDEN + o] = w0;
    Wf[(size_t)i1 * HIDDEN + o] = w1;

    float sc0 = scaler[o * HIDDEN + i0];
    float sc1 = scaler[o * HIDDEN + i1];
#pragma unroll
    for (int c = 0; c < NCOEF; c++) {
        float s0 = spline_w[(o * HIDDEN + i0) * NCOEF + c] * sc0;
        float s1 = spline_w[(o * HIDDEN + i1) * NCOEF + c] * sc1;
        hi = h2_split_hi(s0, s1, lo);
        int kc = 4 + c * 4 + iq;
        Wh[kc * 2048 + o * 16 + kp] = hi;
        Wl[kc * 2048 + o * 16 + kp] = lo;
        Wf[(size_t)(HIDDEN + c * HIDDEN + i0) * HIDDEN + o] = s0;
        Wf[(size_t)(HIDDEN + c * HIDDEN + i1) * HIDDEN + o] = s1;
    }
}

__global__ void prep_protos(const float* __restrict__ protos) {
    int w = (blockIdx.x * blockDim.x + threadIdx.x) >> 5;
    int lane = threadIdx.x & 31;
    if (w >= NPROTO) return;
    float ss = 0.f;
    for (int i = lane; i < HIDDEN; i += 32) {
        float v = protos[w * HIDDEN + i];
        ss += v * v;
    }
#pragma unroll
    for (int off = 16; off; off >>= 1) ss += __shfl_xor_sync(0xffffffffu, ss, off);
    float inv = 1.0f / fmaxf(sqrtf(ss), 1e-8f);
    for (int i = lane; i < HIDDEN; i += 32) {
        float v = protos[w * HIDDEN + i] * inv;
        g_pn[w * HIDDEN + i] = v;
        g_pnT[i * NPROTO + w] = v;
    }
}

__global__ void reset_cnt() { g_cnt = 0; }

// ---------------- fused KAN layer: fp16 2-split 3-term, double-buffered ----------------
// smem u32 view: xs[16384] | A bufs [2][hi2560|lo2560] | B bufs [2][hi2560|lo2560]
#define U_SA  16384
#define U_SB  (16384 + 10240)
#define SM_WORDS (U_SB + 10240)      // 36864 u32 = 147456 B

__global__ void __launch_bounds__(NTHR, 1)
kan_tc(const float* __restrict__ in,
       const uint32_t* __restrict__ Wh, const uint32_t* __restrict__ Wl,
       float* __restrict__ out) {
    extern __shared__ float sm[];
    float* xs = sm;
    uint32_t* u32b = (uint32_t*)sm;

    const int tid  = threadIdx.x;
    const int lane = tid & 31;
    const int wid  = tid >> 5;        // 0..15
    const int wr   = wid >> 2;        // 0..3  rows wr*32
    const int wc   = wid & 3;         // 0..3  cols wc*32
    const int gq   = lane >> 2;       // 0..7
    const int tq   = lane & 3;        // 0..3

    const float g0 = g_gp[0], invh = g_gp[1];
    const int m0 = blockIdx.x * TILE_M;

    {   // x tile load
        const float4* src = (const float4*)(in + (size_t)m0 * HIDDEN);
        float4* dst = (float4*)xs;
#pragma unroll
        for (int j = 0; j < 8; j++) dst[tid + j * NTHR] = src[tid + j * NTHR];
    }
    __syncthreads();

    float acc[2][4][4];
#pragma unroll
    for (int a = 0; a < 2; a++)
#pragma unroll
        for (int b = 0; b < 4; b++)
#pragma unroll
            for (int c = 0; c < 4; c++) acc[a][b][c] = 0.f;

    // ---- stage lambda-ish macro via explicit code ----
    // stage chunk kc into buffer bb
#define STAGE(kc_, bb_) do {                                                         \
        uint32_t* dBh = u32b + U_SB + (bb_) * 5120;                                  \
        uint32_t* dBl = dBh + 2560;                                                  \
        const uint2* sh = (const uint2*)(Wh + (kc_) * 2048);                         \
        const uint2* sl = (const uint2*)(Wl + (kc_) * 2048);                         \
        _Pragma("unroll")                                                            \
        for (int j = 0; j < 2; j++) {                                                \
            int f2 = tid + j * NTHR;                                                 \
            int n = f2 >> 3, kp2 = f2 & 7;                                           \
            ((uint2*)(dBh + n * 20))[kp2] = sh[f2];                                  \
            ((uint2*)(dBl + n * 20))[kp2] = sl[f2];                                  \
        }                                                                            \
        uint32_t* dAh = u32b + U_SA + (bb_) * 5120;                                  \
        uint32_t* dAl = dAh + 2560;                                                  \
        const bool is_silu = (kc_) < 4;                                              \
        int cc = 0, ibase;                                                           \
        if (is_silu) ibase = (kc_) * 32;                                             \
        else { int g = (kc_) - 4; cc = g >> 2; ibase = (g & 3) * 32; }               \
        _Pragma("unroll")                                                            \
        for (int j = 0; j < 4; j++) {                                                \
            int p = tid + j * NTHR;                                                  \
            int r = p >> 4, kp = p & 15;                                             \
            float2 xv = *(const float2*)(xs + r * HIDDEN + ibase + 2 * kp);          \
            float v0, v1;                                                            \
            if (is_silu) {                                                           \
                v0 = xv.x / (1.0f + __expf(-xv.x));                                  \
                v1 = xv.y / (1.0f + __expf(-xv.y));                                  \
            } else {                                                                 \
                v0 = bspline_c(xv.x, cc, g0, invh);                                  \
                v1 = bspline_c(xv.y, cc, g0, invh);                                  \
            }                                                                        \
            uint32_t lo2, hi2 = h2_split_hi(v0, v1, lo2);                            \
            dAh[r * 20 + kp] = hi2;                                                  \
            dAl[r * 20 + kp] = lo2;                                                  \
        }                                                                            \
    } while (0)

    STAGE(0, 0);
    __syncthreads();

    for (int kc = 0; kc < NCHUNK; kc++) {
        const int b = kc & 1;
        if (kc < NCHUNK - 1) STAGE(kc + 1, b ^ 1);

        uint32_t* sAh = u32b + U_SA + b * 5120;
        uint32_t* sAl = sAh + 2560;
        uint32_t* sBh = u32b + U_SB + b * 5120;
        uint32_t* sBl = sBh + 2560;

#pragma unroll
        for (int ks = 0; ks < 2; ks++) {
            const int kb = ks * 8 + tq;
            uint32_t bh[4][2], bl[4][2];
#pragma unroll
            for (int nf = 0; nf < 4; nf++) {
                int col = wc * 32 + nf * 8 + gq;
                bh[nf][0] = sBh[col * 20 + kb];
                bh[nf][1] = sBh[col * 20 + kb + 4];
                bl[nf][0] = sBl[col * 20 + kb];
                bl[nf][1] = sBl[col * 20 + kb + 4];
            }
#pragma unroll
            for (int mf = 0; mf < 2; mf++) {
                int row = wr * 32 + mf * 16 + gq;
                uint32_t ah[4] = { sAh[row * 20 + kb], sAh[(row + 8) * 20 + kb],
                                   sAh[row * 20 + kb + 4], sAh[(row + 8) * 20 + kb + 4] };
                uint32_t al[4] = { sAl[row * 20 + kb], sAl[(row + 8) * 20 + kb],
                                   sAl[row * 20 + kb + 4], sAl[(row + 8) * 20 + kb + 4] };
#pragma unroll
                for (int nf = 0; nf < 4; nf++) {
                    mma16(acc[mf][nf], ah, bh[nf]);
                    mma16(acc[mf][nf], ah, bl[nf]);
                    mma16(acc[mf][nf], al, bh[nf]);
                }
            }
        }
        __syncthreads();
    }

#pragma unroll
    for (int mf = 0; mf < 2; mf++) {
        int row = m0 + wr * 32 + mf * 16 + gq;
#pragma unroll
        for (int nf = 0; nf < 4; nf++) {
            int col = wc * 32 + nf * 8 + tq * 2;
            *(float2*)(out + (size_t)row * HIDDEN + col) =
                make_float2(acc[mf][nf][0], acc[mf][nf][1]);
            *(float2*)(out + (size_t)(row + 8) * HIDDEN + col) =
                make_float2(acc[mf][nf][2], acc[mf][nf][3]);
        }
    }
}

// ---------------- cluster: register-tiled fp32 GEMM + top-2 argmax ----------------
// block: 128 rows x 256 protos; 256 thr; thread = 4 rows (rg*4+j) x 8 protos (jj*8+pg per quarter)
// smem: sR[128][129] | sP[64][129]
__global__ void __launch_bounds__(256, 1)
cluster_kernel(const float* __restrict__ emb, float* __restrict__ assignOut) {
    extern __shared__ float sm[];
    float* sR = sm;                  // 128*129
    float* sP = sm + 128 * 129;      // 64*129

    const int tid = threadIdx.x;
    const int rg  = tid >> 3;        // 0..31
    const int pg  = tid & 7;         // 0..7
    const int base = blockIdx.x * 128;

    for (int l = tid; l < 128 * HIDDEN; l += 256) {
        int r = l >> 7, i = l & 127;
        sR[r * 129 + i] = emb[(size_t)(base + r) * HIDDEN + i];
    }

    float t1[4], t2[4];
    int   i1[4];
#pragma unroll
    for (int j = 0; j < 4; j++) { t1[j] = -3.4e38f; t2[j] = -3.4e38f; i1[j] = 0; }

    for (int pq = 0; pq < 4; pq++) {
        __syncthreads();
        for (int l = tid; l < 64 * HIDDEN; l += 256) {
            int p = l >> 7, i = l & 127;
            sP[p * 129 + i] = g_pn[(size_t)(pq * 64 + p) * HIDDEN + i];
        }
        __syncthreads();

        float acc[4][8];
#pragma unroll
        for (int j = 0; j < 4; j++)
#pragma unroll
            for (int jj = 0; jj < 8; jj++) acc[j][jj] = 0.f;

        const float* rbase = sR + (rg * 4) * 129;
        const float* pbase = sP + pg * 129;
#pragma unroll 4
        for (int k = 0; k < HIDDEN; k++) {
            float rv0 = rbase[k];
            float rv1 = rbase[129 + k];
            float rv2 = rbase[258 + k];
            float rv3 = rbase[387 + k];
#pragma unroll
            for (int jj = 0; jj < 8; jj++) {
                float pv = pbase[jj * 8 * 129 + k];
                acc[0][jj] += rv0 * pv;
                acc[1][jj] += rv1 * pv;
                acc[2][jj] += rv2 * pv;
                acc[3][jj] += rv3 * pv;
            }
        }

#pragma unroll
        for (int j = 0; j < 4; j++) {
#pragma unroll
            for (int jj = 0; jj < 8; jj++) {
                float v = acc[j][jj];
                int idx = pq * 64 + jj * 8 + pg;
                if (v > t1[j]) { t2[j] = t1[j]; t1[j] = v; i1[j] = idx; }
                else if (v > t2[j]) { t2[j] = v; }
            }
        }
    }

    // reduce top-2 across the 8 pg lanes (width-8 shfl groups)
#pragma unroll
    for (int j = 0; j < 4; j++) {
        float a1 = t1[j], a2 = t2[j];
        int   ai = i1[j];
#pragma unroll
        for (int off = 4; off; off >>= 1) {
            float b1 = __shfl_down_sync(0xffffffffu, a1, off, 8);
            float b2 = __shfl_down_sync(0xffffffffu, a2, off, 8);
            int   bi = __shfl_down_sync(0xffffffffu, ai, off, 8);
            if (b1 > a1 || (b1 == a1 && bi < ai)) {
                a2 = fmaxf(a1, b2); a1 = b1; ai = bi;
            } else {
                a2 = fmaxf(a2, b1);
            }
        }
        t1[j] = a1; t2[j] = a2; i1[j] = ai;
    }

    if (pg == 0) {
#pragma unroll
        for (int j = 0; j < 4; j++) {
            int row = base + rg * 4 + j;
            assignOut[row] = (float)i1[j];
            if (t1[j] - t2[j] < TAU) {
                int s = atomicAdd(&g_cnt, 1);
                g_list[s] = row;
            }
        }
    }
}

// ---------------- fp32 fixup: recompute flagged rows end-to-end ----------------
__global__ void __launch_bounds__(256, 1)
fixup_kernel(const float* __restrict__ x,
             const float* __restrict__ Wf1, const float* __restrict__ Wf2,
             float* __restrict__ assignOut) {
    extern __shared__ float sm[];
    float* A  = sm;                 // 36864
    float* hb = sm + 36864;         // 4096
    float* ws = sm + 40960;         // 4096
    __shared__ int ridx[32];
    __shared__ float rv[8];
    __shared__ int   rp[8];

    const int tid = threadIdx.x;
    const int start = blockIdx.x * 32;
    const int cnt = g_cnt;
    if (start >= cnt) return;
    const int nr = min(32, cnt - start);
    if (tid < 32) {
        int srci = start + (tid < nr ? tid : nr - 1);
        ridx[tid] = g_list[srci];
    }
    __syncthreads();

    const float g0 = g_gp[0], invh = g_gp[1];
    const int tr = tid >> 5;
    const int tc = tid & 31;

    float acc[4][4];
    const float* Wf = Wf1;
    const float* src = x;
    bool gather = true;

    for (int layer = 0; layer < 2; layer++) {
        for (int e = tid; e < 32 * HIDDEN; e += 256) {
            int r = e >> 7, i = e & 127;
            float xv = gather ? src[(size_t)ridx[r] * HIDDEN + i] : src[r * HIDDEN + i];
            A[r * KDIM + i] = xv / (1.0f + __expf(-xv));
#pragma unroll
            for (int c = 0; c < NCOEF; c++)
                A[r * KDIM + HIDDEN + c * HIDDEN + i] = bspline_c(xv, c, g0, invh);
        }

#pragma unroll
        for (int a = 0; a < 4; a++)
#pragma unroll
            for (int b = 0; b < 4; b++) acc[a][b] = 0.f;

        for (int k0 = 0; k0 < KDIM; k0 += 32) {
            __syncthreads();
            const float4* gw = (const float4*)(Wf + (size_t)k0 * HIDDEN);
#pragma unroll
            for (int l = 0; l < 4; l++)
                ((float4*)ws)[tid + l * 256] = gw[tid + l * 256];
            __syncthreads();
#pragma unroll
            for (int kk = 0; kk < 32; kk++) {
                float a0 = A[(tr * 4 + 0) * KDIM + k0 + kk];
                float a1 = A[(tr * 4 + 1) * KDIM + k0 + kk];
                float a2 = A[(tr * 4 + 2) * KDIM + k0 + kk];
                float a3 = A[(tr * 4 + 3) * KDIM + k0 + kk];
                float4 w = ((float4*)ws)[kk * 32 + tc];
                acc[0][0] += a0 * w.x; acc[0][1] += a0 * w.y; acc[0][2] += a0 * w.z; acc[0][3] += a0 * w.w;
                acc[1][0] += a1 * w.x; acc[1][1] += a1 * w.y; acc[1][2] += a1 * w.z; acc[1][3] += a1 * w.w;
                acc[2][0] += a2 * w.x; acc[2][1] += a2 * w.y; acc[2][2] += a2 * w.z; acc[2][3] += a2 * w.w;
                acc[3][0] += a3 * w.x; acc[3][1] += a3 * w.y; acc[3][2] += a3 * w.z; acc[3][3] += a3 * w.w;
            }
        }
        __syncthreads();
#pragma unroll
        for (int ri = 0; ri < 4; ri++)
            ((float4*)(hb + (tr * 4 + ri) * HIDDEN))[tc] =
                make_float4(acc[ri][0], acc[ri][1], acc[ri][2], acc[ri][3]);
        __syncthreads();

        Wf = Wf2; src = hb; gather = false;
    }

    float sims[32];
#pragma unroll
    for (int r = 0; r < 32; r++) sims[r] = 0.f;
    for (int i = 0; i < HIDDEN; i++) {
        float pv = g_pnT[i * NPROTO + tid];
#pragma unroll
        for (int r = 0; r < 32; r++) sims[r] += hb[r * HIDDEN + i] * pv;
    }

    for (int r = 0; r < 32; r++) {
        float v = sims[r]; int bi = tid;
#pragma unroll
        for (int off = 16; off; off >>= 1) {
            float ov = __shfl_down_sync(0xffffffffu, v, off);
            int   oi = __shfl_down_sync(0xffffffffu, bi, off);
            if (ov > v || (ov == v && oi < bi)) { v = ov; bi = oi; }
        }
        if ((tid & 31) == 0) { rv[tid >> 5] = v; rp[tid >> 5] = bi; }
        __syncthreads();
        if (tid == 0) {
            float bv = rv[0]; int bb = rp[0];
#pragma unroll
            for (int w = 1; w < 8; w++)
                if (rv[w] > bv || (rv[w] == bv && rp[w] < bb)) { bv = rv[w]; bb = rp[w]; }
            if (r < nr) assignOut[ridx[r]] = (float)bb;
        }
        __syncthreads();
    }
}

// ---------------- launch ----------------
extern "C" void kernel_launch(void* const* d_in, const int* in_sizes, int n_in,
                              void* d_out, int out_size) {
    const float* x         = (const float*)d_in[0];
    const float* protos    = (const float*)d_in[1];
    const float* grid      = (const float*)d_in[2];
    const float* base_w1   = (const float*)d_in[3];
    const float* spline_w1 = (const float*)d_in[4];
    const float* scaler1   = (const float*)d_in[5];
    const float* base_w2   = (const float*)d_in[6];
    const float* spline_w2 = (const float*)d_in[7];
    const float* scaler2   = (const float*)d_in[8];

    int n = in_sizes[0] / HIDDEN;

    uint32_t *Wh1, *Wl1, *Wh2, *Wl2;
    float *Wf1, *Wf2, *h;
    cudaGetSymbolAddress((void**)&Wh1, g_Wh1);
    cudaGetSymbolAddress((void**)&Wl1, g_Wl1);
    cudaGetSymbolAddress((void**)&Wh2, g_Wh2);
    cudaGetSymbolAddress((void**)&Wl2, g_Wl2);
    cudaGetSymbolAddress((void**)&Wf1, g_Wf1);
    cudaGetSymbolAddress((void**)&Wf2, g_Wf2);
    cudaGetSymbolAddress((void**)&h,  g_h);

    prep_grid<<<1, 32>>>(grid);                                              // 0
    prep_weights<<<32, 256>>>(base_w1, spline_w1, scaler1, Wh1, Wl1, Wf1);   // 1
    prep_weights<<<32, 256>>>(base_w2, spline_w2, scaler2, Wh2, Wl2, Wf2);   // 2

    size_t smemL = SM_WORDS * 4;   // 147456 B
    cudaFuncSetAttribute(kan_tc, cudaFuncAttributeMaxDynamicSharedMemorySize, (int)smemL);

    float* emb = (float*)d_out;
    kan_tc<<<n / TILE_M, NTHR, smemL>>>(x, Wh1, Wl1, h);                     // 3  <- ncu capture
    kan_tc<<<n / TILE_M, NTHR, smemL>>>(h, Wh2, Wl2, emb);                   // 4

    if (out_size >= n * HIDDEN + n) {
        float* assign = emb + (size_t)n * HIDDEN;
        prep_protos<<<32, 256>>>(protos);                                    // 5
        reset_cnt<<<1, 32>>>();                                              // 6
        size_t smemC = (size_t)(128 * 129 + 64 * 129) * sizeof(float);       // 99072 B
        cudaFuncSetAttribute(cluster_kernel, cudaFuncAttributeMaxDynamicSharedMemorySize, (int)smemC);
        cluster_kernel<<<n / 128, 256, smemC>>>(emb, assign);                // 7
        size_t smemF = 45056 * sizeof(float);
        cudaFuncSetAttribute(fixup_kernel, cudaFuncAttributeMaxDynamicSharedMemorySize, (int)smemF);
        fixup_kernel<<<(n + 31) / 32, 256, smemF>>>(x, Wf1, Wf2, assign);    // 8
    }
}

// round 10
// speedup vs baseline: 3.1774x; 1.7052x over previous
#include <cuda_runtime.h>
#include <cuda_fp16.h>
#include <cstdint>

#define HIDDEN 128
#define NCOEF  8
#define NPROTO 256
#define NMAX   131072
#define TILE_M 128
#define NCHUNK 36            // 4 silu chunks + 32 spline chunks (4 i-cols x 8 c each)
#define KDIM   1152
#define TAU    4e-4f
#define NTHR   512

// ---------------- device scratch ----------------
__device__ uint32_t g_Wh1[NCHUNK * 2048];
__device__ uint32_t g_Wl1[NCHUNK * 2048];
__device__ uint32_t g_Wh2[NCHUNK * 2048];
__device__ uint32_t g_Wl2[NCHUNK * 2048];
__device__ float g_Wf1[KDIM * HIDDEN];     // fp32 combined, [k][o] (fixup)
__device__ float g_Wf2[KDIM * HIDDEN];
__device__ float g_h[(size_t)NMAX * HIDDEN];
__device__ float g_pn[NPROTO * HIDDEN];
__device__ float g_pnT[HIDDEN * NPROTO];
__device__ float g_gp[2];                  // g0, invh
__device__ int   g_cnt;
__device__ int   g_list[NMAX];

// ---------------- helpers ----------------
__device__ __forceinline__ uint32_t h2_split2(float v0, float v1, uint32_t& lo_out) {
    __half2 hp = __float22half2_rn(make_float2(v0, v1));
    float2 hf = __half22float2(hp);
    __half2 lp = __float22half2_rn(make_float2(v0 - hf.x, v1 - hf.y));
    lo_out = *(uint32_t*)&lp;
    return *(uint32_t*)&hp;
}
__device__ __forceinline__ void mma16(float* c, const uint32_t* a, const uint32_t* b) {
    asm volatile(
        "mma.sync.aligned.m16n8k16.row.col.f32.f16.f16.f32 "
        "{%0,%1,%2,%3}, {%4,%5,%6,%7}, {%8,%9}, {%0,%1,%2,%3};"
        : "+f"(c[0]), "+f"(c[1]), "+f"(c[2]), "+f"(c[3])
        : "r"(a[0]), "r"(a[1]), "r"(a[2]), "r"(a[3]), "r"(b[0]), "r"(b[1]));
}
__device__ __forceinline__ float bspline_c(float xv, int c, float g0, float invh) {
    float t = (xv - g0) * invh;
    float fj = floorf(t);
    float u = t - fj;
    int d = (int)fj - c;
    float v;
    if (d == 0)      v = u * u * u * (1.0f / 6.0f);
    else if (d == 1) v = (1.0f + 3.0f * u + 3.0f * u * u - 3.0f * u * u * u) * (1.0f / 6.0f);
    else if (d == 2) { float w = 1.0f - u; v = (1.0f + 3.0f * w + 3.0f * w * w - 3.0f * w * w * w) * (1.0f / 6.0f); }
    else if (d == 3) { float w = 1.0f - u; v = w * w * w * (1.0f / 6.0f); }
    else             v = 0.0f;
    return v;
}

// ---------------- prep kernels ----------------
__global__ void prep_grid(const float* __restrict__ grid) {
    if (threadIdx.x == 0) {
        g_gp[0] = grid[0];
        g_gp[1] = 1.0f / (grid[1] - grid[0]);
    }
}

// k-layout:
//  silu:   kc = i>>5 (0..3), kp = (i&31)>>1, half-lane = i&1
//  spline: kc = 4 + (i>>2) (4..35), kp = (i&3)*4 + (c>>1), half-lane = c&1
__global__ void prep_weights(const float* __restrict__ base_w,
                             const float* __restrict__ spline_w,
                             const float* __restrict__ scaler,
                             uint32_t* __restrict__ Wh, uint32_t* __restrict__ Wl,
                             float* __restrict__ Wf) {
    int idx = blockIdx.x * blockDim.x + threadIdx.x;
    if (idx >= HIDDEN * 64) return;
    int o = idx >> 6, m = idx & 63;
    int i0 = 2 * m, i1 = 2 * m + 1;
    int iq = m >> 4, kp = m & 15;

    float w0 = base_w[o * HIDDEN + i0];
    float w1 = base_w[o * HIDDEN + i1];
    uint32_t lo, hi = h2_split2(w0, w1, lo);
    Wh[iq * 2048 + o * 16 + kp] = hi;
    Wl[iq * 2048 + o * 16 + kp] = lo;
    Wf[(size_t)i0 * HIDDEN + o] = w0;
    Wf[(size_t)i1 * HIDDEN + o] = w1;

    float sc0 = scaler[o * HIDDEN + i0];
    float sc1 = scaler[o * HIDDEN + i1];
    int kcS = 4 + (i0 >> 2);   // same chunk for i0 and i1 (i0 even)
#pragma unroll
    for (int cp = 0; cp < 4; cp++) {
        float s0 = spline_w[(o * HIDDEN + i0) * NCOEF + 2 * cp]     * sc0;
        float s1 = spline_w[(o * HIDDEN + i0) * NCOEF + 2 * cp + 1] * sc0;
        hi = h2_split2(s0, s1, lo);
        int kp0 = (i0 & 3) * 4 + cp;
        Wh[kcS * 2048 + o * 16 + kp0] = hi;
        Wl[kcS * 2048 + o * 16 + kp0] = lo;
        Wf[(size_t)(HIDDEN + 2 * cp * HIDDEN + i0) * HIDDEN + o]       = s0;
        Wf[(size_t)(HIDDEN + (2 * cp + 1) * HIDDEN + i0) * HIDDEN + o] = s1;
        float s2 = spline_w[(o * HIDDEN + i1) * NCOEF + 2 * cp]     * sc1;
        float s3 = spline_w[(o * HIDDEN + i1) * NCOEF + 2 * cp + 1] * sc1;
        hi = h2_split2(s2, s3, lo);
        int kp1 = (i1 & 3) * 4 + cp;
        Wh[kcS * 2048 + o * 16 + kp1] = hi;
        Wl[kcS * 2048 + o * 16 + kp1] = lo;
        Wf[(size_t)(HIDDEN + 2 * cp * HIDDEN + i1) * HIDDEN + o]       = s2;
        Wf[(size_t)(HIDDEN + (2 * cp + 1) * HIDDEN + i1) * HIDDEN + o] = s3;
    }
}

__global__ void prep_protos(const float* __restrict__ protos) {
    int w = (blockIdx.x * blockDim.x + threadIdx.x) >> 5;
    int lane = threadIdx.x & 31;
    if (w >= NPROTO) return;
    float ss = 0.f;
    for (int i = lane; i < HIDDEN; i += 32) {
        float v = protos[w * HIDDEN + i];
        ss += v * v;
    }
#pragma unroll
    for (int off = 16; off; off >>= 1) ss += __shfl_xor_sync(0xffffffffu, ss, off);
    float inv = 1.0f / fmaxf(sqrtf(ss), 1e-8f);
    for (int i = lane; i < HIDDEN; i += 32) {
        float v = protos[w * HIDDEN + i] * inv;
        g_pn[w * HIDDEN + i] = v;
        g_pnT[i * NPROTO + w] = v;
    }
}

__global__ void reset_cnt() { g_cnt = 0; }

// ---------------- fused KAN layer ----------------
#define U_SA  16384
#define U_SB  (16384 + 10240)
#define SM_WORDS (U_SB + 10240)      // 36864 u32 = 147456 B

__global__ void __launch_bounds__(NTHR, 1)
kan_tc(const float* __restrict__ in,
       const uint32_t* __restrict__ Wh, const uint32_t* __restrict__ Wl,
       float* __restrict__ out) {
    extern __shared__ float sm[];
    float* xs = sm;
    uint32_t* u32b = (uint32_t*)sm;

    const int tid  = threadIdx.x;
    const int lane = tid & 31;
    const int wid  = tid >> 5;        // 0..15
    const int wr   = wid >> 2;        // 0..3  rows wr*32
    const int wc   = wid & 3;         // 0..3  cols wc*32
    const int gq   = lane >> 2;       // 0..7
    const int tq   = lane & 3;        // 0..3

    const float g0 = g_gp[0], invh = g_gp[1];
    const int m0 = blockIdx.x * TILE_M;

    {   // x tile load
        const float4* src = (const float4*)(in + (size_t)m0 * HIDDEN);
        float4* dst = (float4*)xs;
#pragma unroll
        for (int j = 0; j < 8; j++) dst[tid + j * NTHR] = src[tid + j * NTHR];
    }
    __syncthreads();

    float acc[2][4][4];
#pragma unroll
    for (int a = 0; a < 2; a++)
#pragma unroll
        for (int b = 0; b < 4; b++)
#pragma unroll
            for (int c = 0; c < 4; c++) acc[a][b][c] = 0.f;

#define STAGE(kc_, bb_) do {                                                         \
        uint32_t* dBh = u32b + U_SB + (bb_) * 5120;                                  \
        uint32_t* dBl = dBh + 2560;                                                  \
        const uint2* sh = (const uint2*)(Wh + (kc_) * 2048);                         \
        const uint2* sl = (const uint2*)(Wl + (kc_) * 2048);                         \
        _Pragma("unroll")                                                            \
        for (int j = 0; j < 2; j++) {                                                \
            int f2 = tid + j * NTHR;                                                 \
            int n = f2 >> 3, kp2 = f2 & 7;                                           \
            ((uint2*)(dBh + n * 20))[kp2] = sh[f2];                                  \
            ((uint2*)(dBl + n * 20))[kp2] = sl[f2];                                  \
        }                                                                            \
        uint32_t* dAh = u32b + U_SA + (bb_) * 5120;                                  \
        uint32_t* dAl = dAh + 2560;                                                  \
        if ((kc_) < 4) {                                                             \
            int ibase = (kc_) * 32;                                                  \
            _Pragma("unroll")                                                        \
            for (int j = 0; j < 4; j++) {                                            \
                int p = tid + j * NTHR;                                              \
                int r = p >> 4, kp = p & 15;                                         \
                float2 xv = *(const float2*)(xs + r * HIDDEN + ibase + 2 * kp);      \
                float v0 = xv.x / (1.0f + __expf(-xv.x));                            \
                float v1 = xv.y / (1.0f + __expf(-xv.y));                            \
                uint32_t lo2, hi2 = h2_split2(v0, v1, lo2);                          \
                dAh[r * 20 + kp] = hi2;                                              \
                dAl[r * 20 + kp] = lo2;                                              \
            }                                                                        \
        } else {                                                                     \
            int ibase = ((kc_) - 4) * 4;                                             \
            int r = tid >> 2, q = tid & 3;                                           \
            float xv = xs[r * HIDDEN + ibase + q];                                   \
            float t  = (xv - g0) * invh;                                             \
            float fj = floorf(t);                                                    \
            float u  = t - fj;                                                       \
            int jc   = (int)fj;                                                      \
            float u2 = u * u, u3 = u2 * u;                                           \
            float wd0 = u3 * (1.0f / 6.0f);                                          \
            float wd1 = (1.0f + 3.0f * u + 3.0f * u2 - 3.0f * u3) * (1.0f / 6.0f);   \
            float wm = 1.0f - u;                                                     \
            float wm2 = wm * wm;                                                     \
            float wd2 = (1.0f + 3.0f * wm + 3.0f * wm2 - 3.0f * wm2 * wm) * (1.0f / 6.0f); \
            float wd3 = wm2 * wm * (1.0f / 6.0f);                                    \
            float val[8];                                                            \
            _Pragma("unroll")                                                        \
            for (int c = 0; c < 8; c++) {                                            \
                float v = 0.f;                                                       \
                v = (jc == c)     ? wd0 : v;                                         \
                v = (jc == c + 1) ? wd1 : v;                                         \
                v = (jc == c + 2) ? wd2 : v;                                         \
                v = (jc == c + 3) ? wd3 : v;                                         \
                val[c] = v;                                                          \
            }                                                                        \
            _Pragma("unroll")                                                        \
            for (int cp = 0; cp < 4; cp++) {                                         \
                uint32_t lo2, hi2 = h2_split2(val[2 * cp], val[2 * cp + 1], lo2);    \
                dAh[r * 20 + q * 4 + cp] = hi2;                                      \
                dAl[r * 20 + q * 4 + cp] = lo2;                                      \
            }                                                                        \
        }                                                                            \
    } while (0)

    STAGE(0, 0);
    __syncthreads();

    for (int kc = 0; kc < NCHUNK; kc++) {
        const int b = kc & 1;
        if (kc < NCHUNK - 1) STAGE(kc + 1, b ^ 1);

        uint32_t* sAh = u32b + U_SA + b * 5120;
        uint32_t* sAl = sAh + 2560;
        uint32_t* sBh = u32b + U_SB + b * 5120;
        uint32_t* sBl = sBh + 2560;

#pragma unroll
        for (int ks = 0; ks < 2; ks++) {
            const int kb = ks * 8 + tq;
            uint32_t bh[4][2], bl[4][2];
#pragma unroll
            for (int nf = 0; nf < 4; nf++) {
                int col = wc * 32 + nf * 8 + gq;
                bh[nf][0] = sBh[col * 20 + kb];
                bh[nf][1] = sBh[col * 20 + kb + 4];
                bl[nf][0] = sBl[col * 20 + kb];
                bl[nf][1] = sBl[col * 20 + kb + 4];
            }
#pragma unroll
            for (int mf = 0; mf < 2; mf++) {
                int row = wr * 32 + mf * 16 + gq;
                uint32_t ah[4] = { sAh[row * 20 + kb], sAh[(row + 8) * 20 + kb],
                                   sAh[row * 20 + kb + 4], sAh[(row + 8) * 20 + kb + 4] };
                uint32_t al[4] = { sAl[row * 20 + kb], sAl[(row + 8) * 20 + kb],
                                   sAl[row * 20 + kb + 4], sAl[(row + 8) * 20 + kb + 4] };
#pragma unroll
                for (int nf = 0; nf < 4; nf++) {
                    mma16(acc[mf][nf], ah, bh[nf]);
                    mma16(acc[mf][nf], ah, bl[nf]);
                    mma16(acc[mf][nf], al, bh[nf]);
                }
            }
        }
        __syncthreads();
    }

#pragma unroll
    for (int mf = 0; mf < 2; mf++) {
        int row = m0 + wr * 32 + mf * 16 + gq;
#pragma unroll
        for (int nf = 0; nf < 4; nf++) {
            int col = wc * 32 + nf * 8 + tq * 2;
            *(float2*)(out + (size_t)row * HIDDEN + col) =
                make_float2(acc[mf][nf][0], acc[mf][nf][1]);
            *(float2*)(out + (size_t)(row + 8) * HIDDEN + col) =
                make_float2(acc[mf][nf][2], acc[mf][nf][3]);
        }
    }
}

// ---------------- cluster: register-tiled fp32 GEMM + top-2 argmax ----------------
__global__ void __launch_bounds__(256, 1)
cluster_kernel(const float* __restrict__ emb, float* __restrict__ assignOut) {
    extern __shared__ float sm[];
    float* sR = sm;                  // 128*129
    float* sP = sm + 128 * 129;      // 64*129

    const int tid = threadIdx.x;
    const int rg  = tid >> 3;        // 0..31
    const int pg  = tid & 7;         // 0..7
    const int base = blockIdx.x * 128;

    for (int l = tid; l < 128 * HIDDEN; l += 256) {
        int r = l >> 7, i = l & 127;
        sR[r * 129 + i] = emb[(size_t)(base + r) * HIDDEN + i];
    }

    float t1[4], t2[4];
    int   i1[4];
#pragma unroll
    for (int j = 0; j < 4; j++) { t1[j] = -3.4e38f; t2[j] = -3.4e38f; i1[j] = 0; }

    for (int pq = 0; pq < 4; pq++) {
        __syncthreads();
        for (int l = tid; l < 64 * HIDDEN; l += 256) {
            int p = l >> 7, i = l & 127;
            sP[p * 129 + i] = g_pn[(size_t)(pq * 64 + p) * HIDDEN + i];
        }
        __syncthreads();

        float acc[4][8];
#pragma unroll
        for (int j = 0; j < 4; j++)
#pragma unroll
            for (int jj = 0; jj < 8; jj++) acc[j][jj] = 0.f;

        const float* rbase = sR + (rg * 4) * 129;
        const float* pbase = sP + pg * 129;
#pragma unroll 4
        for (int k = 0; k < HIDDEN; k++) {
            float rv0 = rbase[k];
            float rv1 = rbase[129 + k];
            float rv2 = rbase[258 + k];
            float rv3 = rbase[387 + k];
#pragma unroll
            for (int jj = 0; jj < 8; jj++) {
                float pv = pbase[jj * 8 * 129 + k];
                acc[0][jj] += rv0 * pv;
                acc[1][jj] += rv1 * pv;
                acc[2][jj] += rv2 * pv;
                acc[3][jj] += rv3 * pv;
            }
        }

#pragma unroll
        for (int j = 0; j < 4; j++) {
#pragma unroll
            for (int jj = 0; jj < 8; jj++) {
                float v = acc[j][jj];
                int idx = pq * 64 + jj * 8 + pg;
                if (v > t1[j]) { t2[j] = t1[j]; t1[j] = v; i1[j] = idx; }
                else if (v > t2[j]) { t2[j] = v; }
            }
        }
    }

#pragma unroll
    for (int j = 0; j < 4; j++) {
        float a1 = t1[j], a2 = t2[j];
        int   ai = i1[j];
#pragma unroll
        for (int off = 4; off; off >>= 1) {
            float b1 = __shfl_down_sync(0xffffffffu, a1, off, 8);
            float b2 = __shfl_down_sync(0xffffffffu, a2, off, 8);
            int   bi = __shfl_down_sync(0xffffffffu, ai, off, 8);
            if (b1 > a1 || (b1 == a1 && bi < ai)) {
                a2 = fmaxf(a1, b2); a1 = b1; ai = bi;
            } else {
                a2 = fmaxf(a2, b1);
            }
        }
        t1[j] = a1; t2[j] = a2; i1[j] = ai;
    }

    if (pg == 0) {
#pragma unroll
        for (int j = 0; j < 4; j++) {
            int row = base + rg * 4 + j;
            assignOut[row] = (float)i1[j];
            if (t1[j] - t2[j] < TAU) {
                int s = atomicAdd(&g_cnt, 1);
                g_list[s] = row;
            }
        }
    }
}

// ---------------- fp32 fixup ----------------
__global__ void __launch_bounds__(256, 1)
fixup_kernel(const float* __restrict__ x,
             const float* __restrict__ Wf1, const float* __restrict__ Wf2,
             float* __restrict__ assignOut) {
    extern __shared__ float sm[];
    float* A  = sm;                 // 36864
    float* hb = sm + 36864;         // 4096
    float* ws = sm + 40960;         // 4096
    __shared__ int ridx[32];
    __shared__ float rv[8];
    __shared__ int   rp[8];

    const int tid = threadIdx.x;
    const int start = blockIdx.x * 32;
    const int cnt = g_cnt;
    if (start >= cnt) return;
    const int nr = min(32, cnt - start);
    if (tid < 32) {
        int srci = start + (tid < nr ? tid : nr - 1);
        ridx[tid] = g_list[srci];
    }
    __syncthreads();

    const float g0 = g_gp[0], invh = g_gp[1];
    const int tr = tid >> 5;
    const int tc = tid & 31;

    float acc[4][4];
    const float* Wf = Wf1;
    const float* src = x;
    bool gather = true;

    for (int layer = 0; layer < 2; layer++) {
        for (int e = tid; e < 32 * HIDDEN; e += 256) {
            int r = e >> 7, i = e & 127;
            float xv = gather ? src[(size_t)ridx[r] * HIDDEN + i] : src[r * HIDDEN + i];
            A[r * KDIM + i] = xv / (1.0f + __expf(-xv));
#pragma unroll
            for (int c = 0; c < NCOEF; c++)
                A[r * KDIM + HIDDEN + c * HIDDEN + i] = bspline_c(xv, c, g0, invh);
        }

#pragma unroll
        for (int a = 0; a < 4; a++)
#pragma unroll
            for (int b = 0; b < 4; b++) acc[a][b] = 0.f;

        for (int k0 = 0; k0 < KDIM; k0 += 32) {
            __syncthreads();
            const float4* gw = (const float4*)(Wf + (size_t)k0 * HIDDEN);
#pragma unroll
            for (int l = 0; l < 4; l++)
                ((float4*)ws)[tid + l * 256] = gw[tid + l * 256];
            __syncthreads();
#pragma unroll
            for (int kk = 0; kk < 32; kk++) {
                float a0 = A[(tr * 4 + 0) * KDIM + k0 + kk];
                float a1 = A[(tr * 4 + 1) * KDIM + k0 + kk];
                float a2 = A[(tr * 4 + 2) * KDIM + k0 + kk];
                float a3 = A[(tr * 4 + 3) * KDIM + k0 + kk];
                float4 w = ((float4*)ws)[kk * 32 + tc];
                acc[0][0] += a0 * w.x; acc[0][1] += a0 * w.y; acc[0][2] += a0 * w.z; acc[0][3] += a0 * w.w;
                acc[1][0] += a1 * w.x; acc[1][1] += a1 * w.y; acc[1][2] += a1 * w.z; acc[1][3] += a1 * w.w;
                acc[2][0] += a2 * w.x; acc[2][1] += a2 * w.y; acc[2][2] += a2 * w.z; acc[2][3] += a2 * w.w;
                acc[3][0] += a3 * w.x; acc[3][1] += a3 * w.y; acc[3][2] += a3 * w.z; acc[3][3] += a3 * w.w;
            }
        }
        __syncthreads();
#pragma unroll
        for (int ri = 0; ri < 4; ri++)
            ((float4*)(hb + (tr * 4 + ri) * HIDDEN))[tc] =
                make_float4(acc[ri][0], acc[ri][1], acc[ri][2], acc[ri][3]);
        __syncthreads();

        Wf = Wf2; src = hb; gather = false;
    }

    float sims[32];
#pragma unroll
    for (int r = 0; r < 32; r++) sims[r] = 0.f;
    for (int i = 0; i < HIDDEN; i++) {
        float pv = g_pnT[i * NPROTO + tid];
#pragma unroll
        for (int r = 0; r < 32; r++) sims[r] += hb[r * HIDDEN + i] * pv;
    }

    for (int r = 0; r < 32; r++) {
        float v = sims[r]; int bi = tid;
#pragma unroll
        for (int off = 16; off; off >>= 1) {
            float ov = __shfl_down_sync(0xffffffffu, v, off);
            int   oi = __shfl_down_sync(0xffffffffu, bi, off);
            if (ov > v || (ov == v && oi < bi)) { v = ov; bi = oi; }
        }
        if ((tid & 31) == 0) { rv[tid >> 5] = v; rp[tid >> 5] = bi; }
        __syncthreads();
        if (tid == 0) {
            float bv = rv[0]; int bb = rp[0];
#pragma unroll
            for (int w = 1; w < 8; w++)
                if (rv[w] > bv || (rv[w] == bv && rp[w] < bb)) { bv = rv[w]; bb = rp[w]; }
            if (r < nr) assignOut[ridx[r]] = (float)bb;
        }
        __syncthreads();
    }
}

// ---------------- launch ----------------
extern "C" void kernel_launch(void* const* d_in, const int* in_sizes, int n_in,
                              void* d_out, int out_size) {
    const float* x         = (const float*)d_in[0];
    const float* protos    = (const float*)d_in[1];
    const float* grid      = (const float*)d_in[2];
    const float* base_w1   = (const float*)d_in[3];
    const float* spline_w1 = (const float*)d_in[4];
    const float* scaler1   = (const float*)d_in[5];
    const float* base_w2   = (const float*)d_in[6];
    const float* spline_w2 = (const float*)d_in[7];
    const float* scaler2   = (const float*)d_in[8];

    int n = in_sizes[0] / HIDDEN;

    uint32_t *Wh1, *Wl1, *Wh2, *Wl2;
    float *Wf1, *Wf2, *h;
    cudaGetSymbolAddress((void**)&Wh1, g_Wh1);
    cudaGetSymbolAddress((void**)&Wl1, g_Wl1);
    cudaGetSymbolAddress((void**)&Wh2, g_Wh2);
    cudaGetSymbolAddress((void**)&Wl2, g_Wl2);
    cudaGetSymbolAddress((void**)&Wf1, g_Wf1);
    cudaGetSymbolAddress((void**)&Wf2, g_Wf2);
    cudaGetSymbolAddress((void**)&h,  g_h);

    prep_grid<<<1, 32>>>(grid);                                              // 0
    prep_weights<<<32, 256>>>(base_w1, spline_w1, scaler1, Wh1, Wl1, Wf1);   // 1
    prep_weights<<<32, 256>>>(base_w2, spline_w2, scaler2, Wh2, Wl2, Wf2);   // 2

    size_t smemL = SM_WORDS * 4;   // 147456 B
    cudaFuncSetAttribute(kan_tc, cudaFuncAttributeMaxDynamicSharedMemorySize, (int)smemL);

    float* emb = (float*)d_out;
    kan_tc<<<n / TILE_M, NTHR, smemL>>>(x, Wh1, Wl1, h);                     // 3  <- ncu capture
    kan_tc<<<n / TILE_M, NTHR, smemL>>>(h, Wh2, Wl2, emb);                   // 4

    if (out_size >= n * HIDDEN + n) {
        float* assign = emb + (size_t)n * HIDDEN;
        prep_protos<<<32, 256>>>(protos);                                    // 5
        reset_cnt<<<1, 32>>>();                                              // 6
        size_t smemC = (size_t)(128 * 129 + 64 * 129) * sizeof(float);
        cudaFuncSetAttribute(cluster_kernel, cudaFuncAttributeMaxDynamicSharedMemorySize, (int)smemC);
        cluster_kernel<<<n / 128, 256, smemC>>>(emb, assign);                // 7
        size_t smemF = 45056 * sizeof(float);
        cudaFuncSetAttribute(fixup_kernel, cudaFuncAttributeMaxDynamicSharedMemorySize, (int)smemF);
        fixup_kernel<<<(n + 31) / 32, 256, smemF>>>(x, Wf1, Wf2, assign);    // 8
    }
}

// round 11
// speedup vs baseline: 3.2600x; 1.0260x over previous
#include <cuda_runtime.h>
#include <cuda_fp16.h>
#include <cstdint>

#define HIDDEN 128
#define NCOEF  8
#define NPROTO 256
#define NMAX   131072
#define TILE_M 128
#define NCHUNK 36            // 4 silu chunks + 32 spline chunks (4 i-cols x 8 c each)
#define KDIM   1152
#define TAU    4e-4f
#define NTHR   512

// ---------------- device scratch ----------------
__device__ uint32_t g_Wh1[NCHUNK * 2048];
__device__ uint32_t g_Wl1[NCHUNK * 2048];
__device__ uint32_t g_Wh2[NCHUNK * 2048];
__device__ uint32_t g_Wl2[NCHUNK * 2048];
__device__ float g_Wf1[KDIM * HIDDEN];     // fp32 combined, [k][o] (fixup)
__device__ float g_Wf2[KDIM * HIDDEN];
__device__ float g_h[(size_t)NMAX * HIDDEN];
__device__ float g_pn[NPROTO * HIDDEN];
__device__ float g_pnT[HIDDEN * NPROTO];
__device__ float g_gp[2];                  // g0, invh
__device__ int   g_cnt;
__device__ int   g_list[NMAX];

// ---------------- helpers ----------------
__device__ __forceinline__ uint32_t smem_u32p(const void* p) {
    uint32_t a;
    asm("{ .reg .u64 t; cvta.to.shared.u64 t, %1; cvt.u32.u64 %0, t; }" : "=r"(a) : "l"(p));
    return a;
}
__device__ __forceinline__ uint32_t h2_split2(float v0, float v1, uint32_t& lo_out) {
    __half2 hp = __float22half2_rn(make_float2(v0, v1));
    float2 hf = __half22float2(hp);
    __half2 lp = __float22half2_rn(make_float2(v0 - hf.x, v1 - hf.y));
    lo_out = *(uint32_t*)&lp;
    return *(uint32_t*)&hp;
}
__device__ __forceinline__ void mma16(float* c, const uint32_t* a, const uint32_t* b) {
    asm volatile(
        "mma.sync.aligned.m16n8k16.row.col.f32.f16.f16.f32 "
        "{%0,%1,%2,%3}, {%4,%5,%6,%7}, {%8,%9}, {%0,%1,%2,%3};"
        : "+f"(c[0]), "+f"(c[1]), "+f"(c[2]), "+f"(c[3])
        : "r"(a[0]), "r"(a[1]), "r"(a[2]), "r"(a[3]), "r"(b[0]), "r"(b[1]));
}
#define LDSM_X4(r, a)                                                         \
    asm volatile("ldmatrix.sync.aligned.m8n8.x4.shared.b16 {%0,%1,%2,%3}, [%4];" \
        : "=r"((r)[0]), "=r"((r)[1]), "=r"((r)[2]), "=r"((r)[3]) : "r"(a))

__device__ __forceinline__ float bspline_c(float xv, int c, float g0, float invh) {
    float t = (xv - g0) * invh;
    float fj = floorf(t);
    float u = t - fj;
    int d = (int)fj - c;
    float v;
    if (d == 0)      v = u * u * u * (1.0f / 6.0f);
    else if (d == 1) v = (1.0f + 3.0f * u + 3.0f * u * u - 3.0f * u * u * u) * (1.0f / 6.0f);
    else if (d == 2) { float w = 1.0f - u; v = (1.0f + 3.0f * w + 3.0f * w * w - 3.0f * w * w * w) * (1.0f / 6.0f); }
    else if (d == 3) { float w = 1.0f - u; v = w * w * w * (1.0f / 6.0f); }
    else             v = 0.0f;
    return v;
}

// ---------------- prep kernels ----------------
__global__ void prep_grid(const float* __restrict__ grid) {
    if (threadIdx.x == 0) {
        g_gp[0] = grid[0];
        g_gp[1] = 1.0f / (grid[1] - grid[0]);
    }
}

// k-layout:
//  silu:   kc = i>>5 (0..3), kp = (i&31)>>1, half-lane = i&1
//  spline: kc = 4 + (i>>2) (4..35), kp = (i&3)*4 + (c>>1), half-lane = c&1
__global__ void prep_weights(const float* __restrict__ base_w,
                             const float* __restrict__ spline_w,
                             const float* __restrict__ scaler,
                             uint32_t* __restrict__ Wh, uint32_t* __restrict__ Wl,
                             float* __restrict__ Wf) {
    int idx = blockIdx.x * blockDim.x + threadIdx.x;
    if (idx >= HIDDEN * 64) return;
    int o = idx >> 6, m = idx & 63;
    int i0 = 2 * m, i1 = 2 * m + 1;
    int iq = m >> 4, kp = m & 15;

    float w0 = base_w[o * HIDDEN + i0];
    float w1 = base_w[o * HIDDEN + i1];
    uint32_t lo, hi = h2_split2(w0, w1, lo);
    Wh[iq * 2048 + o * 16 + kp] = hi;
    Wl[iq * 2048 + o * 16 + kp] = lo;
    Wf[(size_t)i0 * HIDDEN + o] = w0;
    Wf[(size_t)i1 * HIDDEN + o] = w1;

    float sc0 = scaler[o * HIDDEN + i0];
    float sc1 = scaler[o * HIDDEN + i1];
    int kcS = 4 + (i0 >> 2);   // same chunk for i0 and i1 (i0 even)
#pragma unroll
    for (int cp = 0; cp < 4; cp++) {
        float s0 = spline_w[(o * HIDDEN + i0) * NCOEF + 2 * cp]     * sc0;
        float s1 = spline_w[(o * HIDDEN + i0) * NCOEF + 2 * cp + 1] * sc0;
        hi = h2_split2(s0, s1, lo);
        int kp0 = (i0 & 3) * 4 + cp;
        Wh[kcS * 2048 + o * 16 + kp0] = hi;
        Wl[kcS * 2048 + o * 16 + kp0] = lo;
        Wf[(size_t)(HIDDEN + 2 * cp * HIDDEN + i0) * HIDDEN + o]       = s0;
        Wf[(size_t)(HIDDEN + (2 * cp + 1) * HIDDEN + i0) * HIDDEN + o] = s1;
        float s2 = spline_w[(o * HIDDEN + i1) * NCOEF + 2 * cp]     * sc1;
        float s3 = spline_w[(o * HIDDEN + i1) * NCOEF + 2 * cp + 1] * sc1;
        hi = h2_split2(s2, s3, lo);
        int kp1 = (i1 & 3) * 4 + cp;
        Wh[kcS * 2048 + o * 16 + kp1] = hi;
        Wl[kcS * 2048 + o * 16 + kp1] = lo;
        Wf[(size_t)(HIDDEN + 2 * cp * HIDDEN + i1) * HIDDEN + o]       = s2;
        Wf[(size_t)(HIDDEN + (2 * cp + 1) * HIDDEN + i1) * HIDDEN + o] = s3;
    }
}

__global__ void prep_protos(const float* __restrict__ protos) {
    int w = (blockIdx.x * blockDim.x + threadIdx.x) >> 5;
    int lane = threadIdx.x & 31;
    if (w >= NPROTO) return;
    float ss = 0.f;
    for (int i = lane; i < HIDDEN; i += 32) {
        float v = protos[w * HIDDEN + i];
        ss += v * v;
    }
#pragma unroll
    for (int off = 16; off; off >>= 1) ss += __shfl_xor_sync(0xffffffffu, ss, off);
    float inv = 1.0f / fmaxf(sqrtf(ss), 1e-8f);
    for (int i = lane; i < HIDDEN; i += 32) {
        float v = protos[w * HIDDEN + i] * inv;
        g_pn[w * HIDDEN + i] = v;
        g_pnT[i * NPROTO + w] = v;
    }
}

__global__ void reset_cnt() { g_cnt = 0; }

// ---------------- fused KAN layer ----------------
#define U_SA  16384
#define U_SB  (16384 + 10240)
#define SM_WORDS (U_SB + 10240)      // 36864 u32 = 147456 B

__global__ void __launch_bounds__(NTHR, 1)
kan_tc(const float* __restrict__ in,
       const uint32_t* __restrict__ Wh, const uint32_t* __restrict__ Wl,
       float* __restrict__ out) {
    extern __shared__ float sm[];
    float* xs = sm;
    uint32_t* u32b = (uint32_t*)sm;

    const int tid  = threadIdx.x;
    const int lane = tid & 31;
    const int wid  = tid >> 5;        // 0..15
    const int wr   = wid >> 2;        // 0..3  rows wr*32
    const int wc   = wid & 3;         // 0..3  cols wc*32
    const int gq   = lane >> 2;       // 0..7
    const int tq   = lane & 3;        // 0..3
    (void)gq; (void)tq;

    const float g0 = g_gp[0], invh = g_gp[1];
    const int m0 = blockIdx.x * TILE_M;

    // ldmatrix per-lane address bases (byte offsets into dynamic smem)
    const uint32_t smb = smem_u32p(sm);
    // A x4: m0 rows+0 klo | m1 rows+8 klo | m2 rows+0 khi | m3 rows+8 khi
    const int arow  = wr * 32 + ((lane >> 3) & 1) * 8 + (lane & 7);
    const int akoff = ((lane >> 4) & 1) * 4;
    const uint32_t aAddr0 = smb + 4u * (U_SA + arow * 20 + akoff);
    // B x4: m0 cols+0 klo | m1 cols+0 khi | m2 cols+8 klo | m3 cols+8 khi
    const int bcol  = wc * 32 + ((lane >> 4) & 1) * 8 + (lane & 7);
    const int bkoff = ((lane >> 3) & 1) * 4;
    const uint32_t bAddr0 = smb + 4u * (U_SB + bcol * 20 + bkoff);

    {   // x tile load
        const float4* src = (const float4*)(in + (size_t)m0 * HIDDEN);
        float4* dst = (float4*)xs;
#pragma unroll
        for (int j = 0; j < 8; j++) dst[tid + j * NTHR] = src[tid + j * NTHR];
    }
    __syncthreads();

    float acc[2][4][4];
#pragma unroll
    for (int a = 0; a < 2; a++)
#pragma unroll
        for (int b = 0; b < 4; b++)
#pragma unroll
            for (int c = 0; c < 4; c++) acc[a][b][c] = 0.f;

#define STAGE(kc_, bb_) do {                                                         \
        uint32_t* dBh = u32b + U_SB + (bb_) * 5120;                                  \
        uint32_t* dBl = dBh + 2560;                                                  \
        const uint2* sh = (const uint2*)(Wh + (kc_) * 2048);                         \
        const uint2* sl = (const uint2*)(Wl + (kc_) * 2048);                         \
        _Pragma("unroll")                                                            \
        for (int j = 0; j < 2; j++) {                                                \
            int f2 = tid + j * NTHR;                                                 \
            int n = f2 >> 3, kp2 = f2 & 7;                                           \
            ((uint2*)(dBh + n * 20))[kp2] = sh[f2];                                  \
            ((uint2*)(dBl + n * 20))[kp2] = sl[f2];                                  \
        }                                                                            \
        uint32_t* dAh = u32b + U_SA + (bb_) * 5120;                                  \
        uint32_t* dAl = dAh + 2560;                                                  \
        if ((kc_) < 4) {                                                             \
            int ibase = (kc_) * 32;                                                  \
            _Pragma("unroll")                                                        \
            for (int j = 0; j < 4; j++) {                                            \
                int p = tid + j * NTHR;                                              \
                int r = p >> 4, kp = p & 15;                                         \
                float2 xv = *(const float2*)(xs + r * HIDDEN + ibase + 2 * kp);      \
                float v0 = xv.x / (1.0f + __expf(-xv.x));                            \
                float v1 = xv.y / (1.0f + __expf(-xv.y));                            \
                uint32_t lo2, hi2 = h2_split2(v0, v1, lo2);                          \
                dAh[r * 20 + kp] = hi2;                                              \
                dAl[r * 20 + kp] = lo2;                                              \
            }                                                                        \
        } else {                                                                     \
            int ibase = ((kc_) - 4) * 4;                                             \
            int r = tid >> 2, q = tid & 3;                                           \
            float xv = xs[r * HIDDEN + ibase + q];                                   \
            float t  = (xv - g0) * invh;                                             \
            float fj = floorf(t);                                                    \
            float u  = t - fj;                                                       \
            int jc   = (int)fj;                                                      \
            float u2 = u * u, u3 = u2 * u;                                           \
            float wd0 = u3 * (1.0f / 6.0f);                                          \
            float wd1 = (1.0f + 3.0f * u + 3.0f * u2 - 3.0f * u3) * (1.0f / 6.0f);   \
            float wm = 1.0f - u;                                                     \
            float wm2 = wm * wm;                                                     \
            float wd2 = (1.0f + 3.0f * wm + 3.0f * wm2 - 3.0f * wm2 * wm) * (1.0f / 6.0f); \
            float wd3 = wm2 * wm * (1.0f / 6.0f);                                    \
            float val[8];                                                            \
            _Pragma("unroll")                                                        \
            for (int c = 0; c < 8; c++) {                                            \
                float v = 0.f;                                                       \
                v = (jc == c)     ? wd0 : v;                                         \
                v = (jc == c + 1) ? wd1 : v;                                         \
                v = (jc == c + 2) ? wd2 : v;                                         \
                v = (jc == c + 3) ? wd3 : v;                                         \
                val[c] = v;                                                          \
            }                                                                        \
            _Pragma("unroll")                                                        \
            for (int cp = 0; cp < 4; cp++) {                                         \
                uint32_t lo2, hi2 = h2_split2(val[2 * cp], val[2 * cp + 1], lo2);    \
                dAh[r * 20 + q * 4 + cp] = hi2;                                      \
                dAl[r * 20 + q * 4 + cp] = lo2;                                      \
            }                                                                        \
        }                                                                            \
    } while (0)

    STAGE(0, 0);
    __syncthreads();

    for (int kc = 0; kc < NCHUNK; kc++) {
        const int b = kc & 1;
        if (kc < NCHUNK - 1) STAGE(kc + 1, b ^ 1);

        const uint32_t aB = aAddr0 + (uint32_t)b * 20480u;   // b*5120 u32
        const uint32_t bB = bAddr0 + (uint32_t)b * 20480u;

#pragma unroll
        for (int ks = 0; ks < 2; ks++) {
            const uint32_t kso = (uint32_t)ks * 32u;         // ks*8 u32
            uint32_t bh[8], bl[8];
            LDSM_X4(bh + 0, bB + kso);                        // nf0, nf1 (hi)
            LDSM_X4(bh + 4, bB + 1280u + kso);                // nf2, nf3 (hi)
            LDSM_X4(bl + 0, bB + 10240u + kso);               // nf0, nf1 (lo)
            LDSM_X4(bl + 4, bB + 10240u + 1280u + kso);       // nf2, nf3 (lo)
#pragma unroll
            for (int mf = 0; mf < 2; mf++) {
                uint32_t ah[4], al[4];
                LDSM_X4(ah, aB + (uint32_t)mf * 1280u + kso);
                LDSM_X4(al, aB + 10240u + (uint32_t)mf * 1280u + kso);
#pragma unroll
                for (int nf = 0; nf < 4; nf++) {
                    mma16(acc[mf][nf], ah, bh + nf * 2);
                    mma16(acc[mf][nf], ah, bl + nf * 2);
                    mma16(acc[mf][nf], al, bh + nf * 2);
                }
            }
        }
        __syncthreads();
    }

#pragma unroll
    for (int mf = 0; mf < 2; mf++) {
        int row = m0 + wr * 32 + mf * 16 + (lane >> 2);
#pragma unroll
        for (int nf = 0; nf < 4; nf++) {
            int col = wc * 32 + nf * 8 + (lane & 3) * 2;
            *(float2*)(out + (size_t)row * HIDDEN + col) =
                make_float2(acc[mf][nf][0], acc[mf][nf][1]);
            *(float2*)(out + (size_t)(row + 8) * HIDDEN + col) =
                make_float2(acc[mf][nf][2], acc[mf][nf][3]);
        }
    }
}

// ---------------- cluster: register-tiled fp32 GEMM + top-2 argmax ----------------
__global__ void __launch_bounds__(256, 1)
cluster_kernel(const float* __restrict__ emb, float* __restrict__ assignOut) {
    extern __shared__ float sm[];
    float* sR = sm;                  // 128*129
    float* sP = sm + 128 * 129;      // 64*129

    const int tid = threadIdx.x;
    const int rg  = tid >> 3;        // 0..31
    const int pg  = tid & 7;         // 0..7
    const int base = blockIdx.x * 128;

    for (int l = tid; l < 128 * HIDDEN; l += 256) {
        int r = l >> 7, i = l & 127;
        sR[r * 129 + i] = emb[(size_t)(base + r) * HIDDEN + i];
    }

    float t1[4], t2[4];
    int   i1[4];
#pragma unroll
    for (int j = 0; j < 4; j++) { t1[j] = -3.4e38f; t2[j] = -3.4e38f; i1[j] = 0; }

    for (int pq = 0; pq < 4; pq++) {
        __syncthreads();
        for (int l = tid; l < 64 * HIDDEN; l += 256) {
            int p = l >> 7, i = l & 127;
            sP[p * 129 + i] = g_pn[(size_t)(pq * 64 + p) * HIDDEN + i];
        }
        __syncthreads();

        float acc[4][8];
#pragma unroll
        for (int j = 0; j < 4; j++)
#pragma unroll
            for (int jj = 0; jj < 8; jj++) acc[j][jj] = 0.f;

        const float* rbase = sR + (rg * 4) * 129;
        const float* pbase = sP + pg * 129;
#pragma unroll 4
        for (int k = 0; k < HIDDEN; k++) {
            float rv0 = rbase[k];
            float rv1 = rbase[129 + k];
            float rv2 = rbase[258 + k];
            float rv3 = rbase[387 + k];
#pragma unroll
            for (int jj = 0; jj < 8; jj++) {
                float pv = pbase[jj * 8 * 129 + k];
                acc[0][jj] += rv0 * pv;
                acc[1][jj] += rv1 * pv;
                acc[2][jj] += rv2 * pv;
                acc[3][jj] += rv3 * pv;
            }
        }

#pragma unroll
        for (int j = 0; j < 4; j++) {
#pragma unroll
            for (int jj = 0; jj < 8; jj++) {
                float v = acc[j][jj];
                int idx = pq * 64 + jj * 8 + pg;
                if (v > t1[j]) { t2[j] = t1[j]; t1[j] = v; i1[j] = idx; }
                else if (v > t2[j]) { t2[j] = v; }
            }
        }
    }

#pragma unroll
    for (int j = 0; j < 4; j++) {
        float a1 = t1[j], a2 = t2[j];
        int   ai = i1[j];
#pragma unroll
        for (int off = 4; off; off >>= 1) {
            float b1 = __shfl_down_sync(0xffffffffu, a1, off, 8);
            float b2 = __shfl_down_sync(0xffffffffu, a2, off, 8);
            int   bi = __shfl_down_sync(0xffffffffu, ai, off, 8);
            if (b1 > a1 || (b1 == a1 && bi < ai)) {
                a2 = fmaxf(a1, b2); a1 = b1; ai = bi;
            } else {
                a2 = fmaxf(a2, b1);
            }
        }
        t1[j] = a1; t2[j] = a2; i1[j] = ai;
    }

    if (pg == 0) {
#pragma unroll
        for (int j = 0; j < 4; j++) {
            int row = base + rg * 4 + j;
            assignOut[row] = (float)i1[j];
            if (t1[j] - t2[j] < TAU) {
                int s = atomicAdd(&g_cnt, 1);
                g_list[s] = row;
            }
        }
    }
}

// ---------------- fp32 fixup ----------------
__global__ void __launch_bounds__(256, 1)
fixup_kernel(const float* __restrict__ x,
             const float* __restrict__ Wf1, const float* __restrict__ Wf2,
             float* __restrict__ assignOut) {
    extern __shared__ float sm[];
    float* A  = sm;                 // 36864
    float* hb = sm + 36864;         // 4096
    float* ws = sm + 40960;         // 4096
    __shared__ int ridx[32];
    __shared__ float rv[8];
    __shared__ int   rp[8];

    const int tid = threadIdx.x;
    const int start = blockIdx.x * 32;
    const int cnt = g_cnt;
    if (start >= cnt) return;
    const int nr = min(32, cnt - start);
    if (tid < 32) {
        int srci = start + (tid < nr ? tid : nr - 1);
        ridx[tid] = g_list[srci];
    }
    __syncthreads();

    const float g0 = g_gp[0], invh = g_gp[1];
    const int tr = tid >> 5;
    const int tc = tid & 31;

    float acc[4][4];
    const float* Wf = Wf1;
    const float* src = x;
    bool gather = true;

    for (int layer = 0; layer < 2; layer++) {
        for (int e = tid; e < 32 * HIDDEN; e += 256) {
            int r = e >> 7, i = e & 127;
            float xv = gather ? src[(size_t)ridx[r] * HIDDEN + i] : src[r * HIDDEN + i];
            A[r * KDIM + i] = xv / (1.0f + __expf(-xv));
#pragma unroll
            for (int c = 0; c < NCOEF; c++)
                A[r * KDIM + HIDDEN + c * HIDDEN + i] = bspline_c(xv, c, g0, invh);
        }

#pragma unroll
        for (int a = 0; a < 4; a++)
#pragma unroll
            for (int b = 0; b < 4; b++) acc[a][b] = 0.f;

        for (int k0 = 0; k0 < KDIM; k0 += 32) {
            __syncthreads();
            const float4* gw = (const float4*)(Wf + (size_t)k0 * HIDDEN);
#pragma unroll
            for (int l = 0; l < 4; l++)
                ((float4*)ws)[tid + l * 256] = gw[tid + l * 256];
            __syncthreads();
#pragma unroll
            for (int kk = 0; kk < 32; kk++) {
                float a0 = A[(tr * 4 + 0) * KDIM + k0 + kk];
                float a1 = A[(tr * 4 + 1) * KDIM + k0 + kk];
                float a2 = A[(tr * 4 + 2) * KDIM + k0 + kk];
                float a3 = A[(tr * 4 + 3) * KDIM + k0 + kk];
                float4 w = ((float4*)ws)[kk * 32 + tc];
                acc[0][0] += a0 * w.x; acc[0][1] += a0 * w.y; acc[0][2] += a0 * w.z; acc[0][3] += a0 * w.w;
                acc[1][0] += a1 * w.x; acc[1][1] += a1 * w.y; acc[1][2] += a1 * w.z; acc[1][3] += a1 * w.w;
                acc[2][0] += a2 * w.x; acc[2][1] += a2 * w.y; acc[2][2] += a2 * w.z; acc[2][3] += a2 * w.w;
                acc[3][0] += a3 * w.x; acc[3][1] += a3 * w.y; acc[3][2] += a3 * w.z; acc[3][3] += a3 * w.w;
            }
        }
        __syncthreads();
#pragma unroll
        for (int ri = 0; ri < 4; ri++)
            ((float4*)(hb + (tr * 4 + ri) * HIDDEN))[tc] =
                make_float4(acc[ri][0], acc[ri][1], acc[ri][2], acc[ri][3]);
        __syncthreads();

        Wf = Wf2; src = hb; gather = false;
    }

    float sims[32];
#pragma unroll
    for (int r = 0; r < 32; r++) sims[r] = 0.f;
    for (int i = 0; i < HIDDEN; i++) {
        float pv = g_pnT[i * NPROTO + tid];
#pragma unroll
        for (int r = 0; r < 32; r++) sims[r] += hb[r * HIDDEN + i] * pv;
    }

    for (int r = 0; r < 32; r++) {
        float v = sims[r]; int bi = tid;
#pragma unroll
        for (int off = 16; off; off >>= 1) {
            float ov = __shfl_down_sync(0xffffffffu, v, off);
            int   oi = __shfl_down_sync(0xffffffffu, bi, off);
            if (ov > v || (ov == v && oi < bi)) { v = ov; bi = oi; }
        }
        if ((tid & 31) == 0) { rv[tid >> 5] = v; rp[tid >> 5] = bi; }
        __syncthreads();
        if (tid == 0) {
            float bv = rv[0]; int bb = rp[0];
#pragma unroll
            for (int w = 1; w < 8; w++)
                if (rv[w] > bv || (rv[w] == bv && rp[w] < bb)) { bv = rv[w]; bb = rp[w]; }
            if (r < nr) assignOut[ridx[r]] = (float)bb;
        }
        __syncthreads();
    }
}

// ---------------- launch ----------------
extern "C" void kernel_launch(void* const* d_in, const int* in_sizes, int n_in,
                              void* d_out, int out_size) {
    const float* x         = (const float*)d_in[0];
    const float* protos    = (const float*)d_in[1];
    const float* grid      = (const float*)d_in[2];
    const float* base_w1   = (const float*)d_in[3];
    const float* spline_w1 = (const float*)d_in[4];
    const float* scaler1   = (const float*)d_in[5];
    const float* base_w2   = (const float*)d_in[6];
    const float* spline_w2 = (const float*)d_in[7];
    const float* scaler2   = (const float*)d_in[8];

    int n = in_sizes[0] / HIDDEN;

    uint32_t *Wh1, *Wl1, *Wh2, *Wl2;
    float *Wf1, *Wf2, *h;
    cudaGetSymbolAddress((void**)&Wh1, g_Wh1);
    cudaGetSymbolAddress((void**)&Wl1, g_Wl1);
    cudaGetSymbolAddress((void**)&Wh2, g_Wh2);
    cudaGetSymbolAddress((void**)&Wl2, g_Wl2);
    cudaGetSymbolAddress((void**)&Wf1, g_Wf1);
    cudaGetSymbolAddress((void**)&Wf2, g_Wf2);
    cudaGetSymbolAddress((void**)&h,  g_h);

    prep_grid<<<1, 32>>>(grid);                                              // 0
    prep_weights<<<32, 256>>>(base_w1, spline_w1, scaler1, Wh1, Wl1, Wf1);   // 1
    prep_weights<<<32, 256>>>(base_w2, spline_w2, scaler2, Wh2, Wl2, Wf2);   // 2

    size_t smemL = SM_WORDS * 4;   // 147456 B
    cudaFuncSetAttribute(kan_tc, cudaFuncAttributeMaxDynamicSharedMemorySize, (int)smemL);

    float* emb = (float*)d_out;
    kan_tc<<<n / TILE_M, NTHR, smemL>>>(x, Wh1, Wl1, h);                     // 3  <- ncu capture
    kan_tc<<<n / TILE_M, NTHR, smemL>>>(h, Wh2, Wl2, emb);                   // 4

    if (out_size >= n * HIDDEN + n) {
        float* assign = emb + (size_t)n * HIDDEN;
        prep_protos<<<32, 256>>>(protos);                                    // 5
        reset_cnt<<<1, 32>>>();                                              // 6
        size_t smemC = (size_t)(128 * 129 + 64 * 129) * sizeof(float);
        cudaFuncSetAttribute(cluster_kernel, cudaFuncAttributeMaxDynamicSharedMemorySize, (int)smemC);
        cluster_kernel<<<n / 128, 256, smemC>>>(emb, assign);                // 7
        size_t smemF = 45056 * sizeof(float);
        cudaFuncSetAttribute(fixup_kernel, cudaFuncAttributeMaxDynamicSharedMemorySize, (int)smemF);
        fixup_kernel<<<(n + 31) / 32, 256, smemF>>>(x, Wf1, Wf2, assign);    // 8
    }
}